// round 1
// baseline (speedup 1.0000x reference)
#include <cuda_runtime.h>

// Problem constants
#define B_ 4
#define S_ 1024
#define D_ 1024
#define H_ 16
#define DH_ 64
#define M_TOT (B_ * S_)   // 4096
#define N_TOT D_          // 1024
#define K_TOT D_          // 1024

// Scratch (allocation-free rule: __device__ globals)
__device__ float g_q[M_TOT * D_];
__device__ float g_k[M_TOT * D_];
__device__ float g_v[M_TOT * D_];
__device__ float g_att[M_TOT * D_];

// ---------------------------------------------------------------------------
// Generic GEMM: Y[M,N] = X[M,K] @ W[N,K]^T + bias[N]
// M=4096, N=1024, K=1024 fixed. 128x128x16 tiles, 8x8 microtile, 256 threads.
// ---------------------------------------------------------------------------
__global__ __launch_bounds__(256) void gemm_bias_kernel(
    const float* __restrict__ X, const float* __restrict__ W,
    const float* __restrict__ bias, float* __restrict__ Y) {
  __shared__ float As[16][132];  // pad 132 -> 2-way max on transpose stores
  __shared__ float Bs[16][132];

  const int tid = threadIdx.x;
  const int tx = tid & 15;       // n-dim
  const int ty = tid >> 4;       // m-dim
  const int m0 = blockIdx.y * 128;
  const int n0 = blockIdx.x * 128;

  const int lr = tid >> 2;        // 0..63
  const int lc = (tid & 3) << 2;  // 0,4,8,12

  float acc[8][8];
#pragma unroll
  for (int i = 0; i < 8; i++)
#pragma unroll
    for (int j = 0; j < 8; j++) acc[i][j] = 0.f;

  const float* Xp = X + (size_t)(m0 + lr) * K_TOT + lc;
  const float* Wp = W + (size_t)(n0 + lr) * K_TOT + lc;

  for (int k0 = 0; k0 < K_TOT; k0 += 16) {
#pragma unroll
    for (int r = 0; r < 2; r++) {
      const int mloc = lr + r * 64;
      float4 t = *(const float4*)(Xp + (size_t)r * 64 * K_TOT + k0);
      As[lc + 0][mloc] = t.x; As[lc + 1][mloc] = t.y;
      As[lc + 2][mloc] = t.z; As[lc + 3][mloc] = t.w;
      float4 u = *(const float4*)(Wp + (size_t)r * 64 * K_TOT + k0);
      Bs[lc + 0][mloc] = u.x; Bs[lc + 1][mloc] = u.y;
      Bs[lc + 2][mloc] = u.z; Bs[lc + 3][mloc] = u.w;
    }
    __syncthreads();
#pragma unroll
    for (int kk = 0; kk < 16; kk++) {
      float4 a0 = *(const float4*)&As[kk][ty * 8];
      float4 a1 = *(const float4*)&As[kk][ty * 8 + 4];
      float4 b0 = *(const float4*)&Bs[kk][tx * 8];
      float4 b1 = *(const float4*)&Bs[kk][tx * 8 + 4];
      float a[8] = {a0.x, a0.y, a0.z, a0.w, a1.x, a1.y, a1.z, a1.w};
      float b[8] = {b0.x, b0.y, b0.z, b0.w, b1.x, b1.y, b1.z, b1.w};
#pragma unroll
      for (int i = 0; i < 8; i++)
#pragma unroll
        for (int j = 0; j < 8; j++) acc[i][j] = fmaf(a[i], b[j], acc[i][j]);
    }
    __syncthreads();
  }

  float4 bv0 = *(const float4*)(bias + n0 + tx * 8);
  float4 bv1 = *(const float4*)(bias + n0 + tx * 8 + 4);
#pragma unroll
  for (int i = 0; i < 8; i++) {
    float* yp = Y + (size_t)(m0 + ty * 8 + i) * N_TOT + n0 + tx * 8;
    float4 o0 = make_float4(acc[i][0] + bv0.x, acc[i][1] + bv0.y,
                            acc[i][2] + bv0.z, acc[i][3] + bv0.w);
    float4 o1 = make_float4(acc[i][4] + bv1.x, acc[i][5] + bv1.y,
                            acc[i][6] + bv1.z, acc[i][7] + bv1.w);
    *(float4*)yp = o0;
    *(float4*)(yp + 4) = o1;
  }
}

// ---------------------------------------------------------------------------
// Fused flash attention.
// Block = one (b,h) and a 128-row Q tile. K-tiles of 64. Online softmax.
// Thread layout: 256 = 16(ty: q-groups of 8) x 16(tx).
//   QK phase: S frag [8 q][4 k], k = tx + 16*j
//   PV phase: O frag [8 q][4 d], d = tx + 16*j
// Smem layout (floats), padded for conflict-free access:
//   Qs[64][129]  (Q^T: [d][q])
//   Ks[64][65]   (K^T: [d][k])
//   Vs[64][68]   ([k][d], float4-aligned rows)
//   Ps[128][64]  ([q][k])
//   mb[64]       (1.0f if key masked)
// ---------------------------------------------------------------------------
#define TQ 128
#define TK 64
#define QS_RL 129
#define KS_RL 65
#define VS_RL 68
#define PS_RL 64
#define QS_OFF 0
#define KS_OFF (64 * QS_RL)                 // 8256
#define VS_OFF (KS_OFF + 64 * KS_RL)        // 12416
#define PS_OFF (VS_OFF + 64 * VS_RL)        // 16768
#define MB_OFF (PS_OFF + TQ * PS_RL)        // 24960
#define ATTN_SMEM_FLOATS (MB_OFF + TK)      // 25024
#define ATTN_SMEM_BYTES (ATTN_SMEM_FLOATS * 4)  // 100096

__global__ __launch_bounds__(256, 2) void attn_kernel(
    const float* __restrict__ Qp, const float* __restrict__ Kp,
    const float* __restrict__ Vp, const unsigned* __restrict__ mask,
    const unsigned* __restrict__ semask, float* __restrict__ Out) {
  extern __shared__ float sm[];

  const int tid = threadIdx.x;
  const int tx = tid & 15;
  const int ty = tid >> 4;
  const int b = blockIdx.z;
  const int h = blockIdx.y;
  const int q0 = blockIdx.x * TQ;
  const size_t hb = ((size_t)b * S_) * D_ + (size_t)h * DH_;

  // Load Q tile transposed: Qs[d][q]
  {
    const int q = tid >> 1;
    const int d0 = (tid & 1) * 32;
    const float* src = Qp + hb + (size_t)(q0 + q) * D_ + d0;
#pragma unroll
    for (int c = 0; c < 32; c += 4) {
      float4 t = *(const float4*)(src + c);
      sm[QS_OFF + (d0 + c + 0) * QS_RL + q] = t.x;
      sm[QS_OFF + (d0 + c + 1) * QS_RL + q] = t.y;
      sm[QS_OFF + (d0 + c + 2) * QS_RL + q] = t.z;
      sm[QS_OFF + (d0 + c + 3) * QS_RL + q] = t.w;
    }
  }

  float m_i[8], l_i[8], O[8][4];
#pragma unroll
  for (int i = 0; i < 8; i++) {
    m_i[i] = -1e30f;
    l_i[i] = 0.f;
#pragma unroll
    for (int j = 0; j < 4; j++) O[i][j] = 0.f;
  }

  const unsigned* mk = mask + (size_t)b * S_;
  const unsigned* smk = semask + (size_t)b * S_;
  const float scale = 0.125f;  // 1/sqrt(64)

  for (int kt = 0; kt < S_; kt += TK) {
    __syncthreads();  // prior PV done; first iter: nothing pending on K/V
    // Load K (transposed) + V + mask flags
    {
      const int k = tid >> 2;
      const int d0 = (tid & 3) * 16;
      const float* ksrc = Kp + hb + (size_t)(kt + k) * D_ + d0;
      const float* vsrc = Vp + hb + (size_t)(kt + k) * D_ + d0;
#pragma unroll
      for (int c = 0; c < 16; c += 4) {
        float4 t = *(const float4*)(ksrc + c);
        sm[KS_OFF + (d0 + c + 0) * KS_RL + k] = t.x;
        sm[KS_OFF + (d0 + c + 1) * KS_RL + k] = t.y;
        sm[KS_OFF + (d0 + c + 2) * KS_RL + k] = t.z;
        sm[KS_OFF + (d0 + c + 3) * KS_RL + k] = t.w;
        float4 u = *(const float4*)(vsrc + c);
        *(float4*)&sm[VS_OFF + k * VS_RL + d0 + c] = u;
      }
      if (tid < TK) {
        sm[MB_OFF + tid] = (mk[kt + tid] | smk[kt + tid]) ? 1.0f : 0.0f;
      }
    }
    __syncthreads();

    // S = Q K^T (fp32)
    float Sf[8][4];
#pragma unroll
    for (int i = 0; i < 8; i++)
#pragma unroll
      for (int j = 0; j < 4; j++) Sf[i][j] = 0.f;

#pragma unroll 8
    for (int d = 0; d < DH_; d++) {
      float a[8], bb[4];
#pragma unroll
      for (int i = 0; i < 8; i++) a[i] = sm[QS_OFF + d * QS_RL + ty * 8 + i];
#pragma unroll
      for (int j = 0; j < 4; j++) bb[j] = sm[KS_OFF + d * KS_RL + tx + 16 * j];
#pragma unroll
      for (int i = 0; i < 8; i++)
#pragma unroll
        for (int j = 0; j < 4; j++) Sf[i][j] = fmaf(a[i], bb[j], Sf[i][j]);
    }

    // scale + mask (mask replaces with exactly -1e9, matching reference)
    float mbv[4];
#pragma unroll
    for (int j = 0; j < 4; j++) mbv[j] = sm[MB_OFF + tx + 16 * j];
#pragma unroll
    for (int i = 0; i < 8; i++)
#pragma unroll
      for (int j = 0; j < 4; j++) {
        float s = Sf[i][j] * scale;
        Sf[i][j] = (mbv[j] != 0.f) ? -1e9f : s;
      }

    // Online softmax update (row stats across 16-lane tx groups)
#pragma unroll
    for (int i = 0; i < 8; i++) {
      float rm = fmaxf(fmaxf(Sf[i][0], Sf[i][1]), fmaxf(Sf[i][2], Sf[i][3]));
#pragma unroll
      for (int off = 8; off > 0; off >>= 1)
        rm = fmaxf(rm, __shfl_xor_sync(0xffffffffu, rm, off));
      const float mn = fmaxf(m_i[i], rm);
      float p[4];
      float rs = 0.f;
#pragma unroll
      for (int j = 0; j < 4; j++) {
        p[j] = __expf(Sf[i][j] - mn);
        rs += p[j];
      }
#pragma unroll
      for (int off = 8; off > 0; off >>= 1)
        rs += __shfl_xor_sync(0xffffffffu, rs, off);
      const float alpha = __expf(m_i[i] - mn);
      l_i[i] = l_i[i] * alpha + rs;
      m_i[i] = mn;
#pragma unroll
      for (int j = 0; j < 4; j++) {
        O[i][j] *= alpha;
        sm[PS_OFF + (ty * 8 + i) * PS_RL + tx + 16 * j] = p[j];
      }
    }
    __syncthreads();  // Ps visible to all

    // O += P @ V
#pragma unroll 4
    for (int kk = 0; kk < TK; kk++) {
      float p[8], v[4];
#pragma unroll
      for (int i = 0; i < 8; i++) p[i] = sm[PS_OFF + (ty * 8 + i) * PS_RL + kk];
#pragma unroll
      for (int j = 0; j < 4; j++) v[j] = sm[VS_OFF + kk * VS_RL + tx + 16 * j];
#pragma unroll
      for (int i = 0; i < 8; i++)
#pragma unroll
        for (int j = 0; j < 4; j++) O[i][j] = fmaf(p[i], v[j], O[i][j]);
    }
  }

  // Epilogue: normalize and write merged-head layout [b, s, h*64 + d]
#pragma unroll
  for (int i = 0; i < 8; i++) {
    const float inv = 1.f / l_i[i];
    float* op = Out + hb + (size_t)(q0 + ty * 8 + i) * D_;
#pragma unroll
    for (int j = 0; j < 4; j++) op[tx + 16 * j] = O[i][j] * inv;
  }
}

// ---------------------------------------------------------------------------
// Launch: 3 projection GEMMs -> fused attention -> output GEMM
// ---------------------------------------------------------------------------
extern "C" void kernel_launch(void* const* d_in, const int* in_sizes, int n_in,
                              void* d_out, int out_size) {
  const float* v = (const float*)d_in[0];
  const float* k = (const float*)d_in[1];
  const float* q = (const float*)d_in[2];
  const unsigned* mask = (const unsigned*)d_in[3];
  const unsigned* semask = (const unsigned*)d_in[4];
  const float* Wv = (const float*)d_in[5];
  const float* bv = (const float*)d_in[6];
  const float* Wk = (const float*)d_in[7];
  const float* bk = (const float*)d_in[8];
  const float* Wq = (const float*)d_in[9];
  const float* bq = (const float*)d_in[10];
  const float* Wm = (const float*)d_in[11];
  const float* bm = (const float*)d_in[12];
  float* out = (float*)d_out;

  float *gq, *gk, *gv, *ga;
  cudaGetSymbolAddress((void**)&gq, g_q);
  cudaGetSymbolAddress((void**)&gk, g_k);
  cudaGetSymbolAddress((void**)&gv, g_v);
  cudaGetSymbolAddress((void**)&ga, g_att);

  cudaFuncSetAttribute(attn_kernel, cudaFuncAttributeMaxDynamicSharedMemorySize,
                       ATTN_SMEM_BYTES);

  const dim3 gemm_grid(N_TOT / 128, M_TOT / 128);  // (8, 32)
  const dim3 blk(256);

  gemm_bias_kernel<<<gemm_grid, blk>>>(v, Wv, bv, gv);
  gemm_bias_kernel<<<gemm_grid, blk>>>(k, Wk, bk, gk);
  gemm_bias_kernel<<<gemm_grid, blk>>>(q, Wq, bq, gq);

  attn_kernel<<<dim3(S_ / TQ, H_, B_), blk, ATTN_SMEM_BYTES>>>(gq, gk, gv, mask,
                                                               semask, ga);

  gemm_bias_kernel<<<gemm_grid, blk>>>(ga, Wm, bm, out);
}

// round 2
// speedup vs baseline: 1.4461x; 1.4461x over previous
#include <cuda_runtime.h>
#include <cuda_bf16.h>

// Problem constants
#define B_ 4
#define S_ 1024
#define D_ 1024
#define H_ 16
#define DH_ 64
#define M_TOT (B_ * S_)   // 4096
#define N_TOT D_          // 1024
#define K_TOT D_          // 1024

// Scratch (allocation-free rule: __device__ globals)
__device__ float g_q[M_TOT * D_];
__device__ float g_k[M_TOT * D_];
__device__ float g_v[M_TOT * D_];
__device__ float g_att[M_TOT * D_];
// bf16 hi/lo staging (reused sequentially for each GEMM)
__device__ __nv_bfloat16 g_xhi[M_TOT * K_TOT];
__device__ __nv_bfloat16 g_xlo[M_TOT * K_TOT];
__device__ __nv_bfloat16 g_whi[N_TOT * K_TOT];
__device__ __nv_bfloat16 g_wlo[N_TOT * K_TOT];

// ---------------------------------------------------------------------------
// fp32 -> (bf16 hi, bf16 lo) split conversion.  x ~= hi + lo, |err| ~ 2^-17|x|
// ---------------------------------------------------------------------------
__global__ __launch_bounds__(256) void cvt_split_kernel(
    const float4* __restrict__ x, __nv_bfloat162* __restrict__ hi,
    __nv_bfloat162* __restrict__ lo, int n4) {
  int i = blockIdx.x * blockDim.x + threadIdx.x;
  if (i >= n4) return;
  float4 t = x[i];
  __nv_bfloat16 h0 = __float2bfloat16(t.x);
  __nv_bfloat16 h1 = __float2bfloat16(t.y);
  __nv_bfloat16 h2 = __float2bfloat16(t.z);
  __nv_bfloat16 h3 = __float2bfloat16(t.w);
  __nv_bfloat16 l0 = __float2bfloat16(t.x - __bfloat162float(h0));
  __nv_bfloat16 l1 = __float2bfloat16(t.y - __bfloat162float(h1));
  __nv_bfloat16 l2 = __float2bfloat16(t.z - __bfloat162float(h2));
  __nv_bfloat16 l3 = __float2bfloat16(t.w - __bfloat162float(h3));
  hi[i * 2 + 0] = __halves2bfloat162(h0, h1);
  hi[i * 2 + 1] = __halves2bfloat162(h2, h3);
  lo[i * 2 + 0] = __halves2bfloat162(l0, l1);
  lo[i * 2 + 1] = __halves2bfloat162(l2, l3);
}

// ---------------------------------------------------------------------------
// Tensor-core GEMM: Y[M,N] = X[M,K] @ W[N,K]^T + bias, X/W given as bf16 hi/lo.
// acc = Xhi*Whi + Xhi*Wlo + Xlo*Whi  (3x mma.sync.m16n8k16, fp32 accum)
// Block 128x128, k-chunk 32, 8 warps (warp tile 64x32), cp.async dbl-buffer.
// ---------------------------------------------------------------------------
#define GKP 40                       // padded halves per smem row (80B: 16B-aligned, ldmatrix conflict-free)
#define SA_HI_B 0
#define SA_LO_B (128 * GKP * 2)      // 10240
#define SB_HI_B (2 * 128 * GKP * 2)  // 20480
#define SB_LO_B (3 * 128 * GKP * 2)  // 30720
#define GBUF_B (4 * 128 * GKP * 2)   // 40960
#define GEMM_SMEM_BYTES (2 * GBUF_B) // 81920

__device__ __forceinline__ void cp16(unsigned dst, const void* src) {
  asm volatile("cp.async.cg.shared.global [%0], [%1], 16;\n" ::"r"(dst),
               "l"(src));
}
__device__ __forceinline__ void ldm4(unsigned addr, unsigned* r) {
  asm volatile("ldmatrix.sync.aligned.m8n8.x4.shared.b16 {%0,%1,%2,%3}, [%4];"
               : "=r"(r[0]), "=r"(r[1]), "=r"(r[2]), "=r"(r[3])
               : "r"(addr));
}
__device__ __forceinline__ void ldm2(unsigned addr, unsigned* r) {
  asm volatile("ldmatrix.sync.aligned.m8n8.x2.shared.b16 {%0,%1}, [%2];"
               : "=r"(r[0]), "=r"(r[1])
               : "r"(addr));
}
__device__ __forceinline__ void mma16816(float* c, const unsigned* a,
                                         const unsigned* b) {
  asm volatile(
      "mma.sync.aligned.m16n8k16.row.col.f32.bf16.bf16.f32 "
      "{%0,%1,%2,%3},{%4,%5,%6,%7},{%8,%9},{%0,%1,%2,%3};"
      : "+f"(c[0]), "+f"(c[1]), "+f"(c[2]), "+f"(c[3])
      : "r"(a[0]), "r"(a[1]), "r"(a[2]), "r"(a[3]), "r"(b[0]), "r"(b[1]));
}

__global__ __launch_bounds__(256, 1) void gemm_mma_kernel(
    const __nv_bfloat16* __restrict__ Ahi, const __nv_bfloat16* __restrict__ Alo,
    const __nv_bfloat16* __restrict__ Bhi, const __nv_bfloat16* __restrict__ Blo,
    const float* __restrict__ bias, float* __restrict__ Y) {
  extern __shared__ __nv_bfloat16 sh[];
  const int tid = threadIdx.x;
  const int lane = tid & 31;
  const int warp = tid >> 5;
  const int wm = warp >> 2;  // 0-1
  const int wn = warp & 3;   // 0-3
  const int m0 = blockIdx.y * 128;
  const int n0 = blockIdx.x * 128;

  const int lrow = tid >> 1;         // 0..127
  const int lcol = (tid & 1) * 16;   // halves within 32-chunk

  const unsigned sbase = (unsigned)__cvta_generic_to_shared(sh);
  const unsigned sdst = sbase + (unsigned)(lrow * GKP + lcol) * 2;

  const __nv_bfloat16* gAh = Ahi + (size_t)(m0 + lrow) * K_TOT + lcol;
  const __nv_bfloat16* gAl = Alo + (size_t)(m0 + lrow) * K_TOT + lcol;
  const __nv_bfloat16* gBh = Bhi + (size_t)(n0 + lrow) * K_TOT + lcol;
  const __nv_bfloat16* gBl = Blo + (size_t)(n0 + lrow) * K_TOT + lcol;

  float acc[4][4][4];
#pragma unroll
  for (int i = 0; i < 4; i++)
#pragma unroll
    for (int j = 0; j < 4; j++)
#pragma unroll
      for (int c = 0; c < 4; c++) acc[i][j][c] = 0.f;

  // ldmatrix per-lane offsets (bytes)
  const unsigned aoff = (unsigned)(((lane & 15) * GKP + ((lane >> 4) & 1) * 8) * 2);
  const unsigned boff = (unsigned)(((lane & 7) * GKP + ((lane >> 3) & 1) * 8) * 2);

#define GEMM_ISSUE(k0, buf)                                     \
  {                                                             \
    unsigned d = sdst + (buf) * GBUF_B;                         \
    cp16(d + SA_HI_B, gAh + (k0));                              \
    cp16(d + SA_HI_B + 16, gAh + (k0) + 8);                     \
    cp16(d + SA_LO_B, gAl + (k0));                              \
    cp16(d + SA_LO_B + 16, gAl + (k0) + 8);                     \
    cp16(d + SB_HI_B, gBh + (k0));                              \
    cp16(d + SB_HI_B + 16, gBh + (k0) + 8);                     \
    cp16(d + SB_LO_B, gBl + (k0));                              \
    cp16(d + SB_LO_B + 16, gBl + (k0) + 8);                     \
    asm volatile("cp.async.commit_group;\n");                   \
  }

  GEMM_ISSUE(0, 0)

  const int NCHUNK = K_TOT / 32;  // 32
  int buf = 0;
  for (int t = 0; t < NCHUNK; t++) {
    if (t + 1 < NCHUNK) {
      GEMM_ISSUE((t + 1) * 32, buf ^ 1)
      asm volatile("cp.async.wait_group 1;\n");
    } else {
      asm volatile("cp.async.wait_group 0;\n");
    }
    __syncthreads();

    const unsigned base = sbase + buf * GBUF_B;
#pragma unroll
    for (int kk = 0; kk < 2; kk++) {
      const unsigned kadd = kk * 32;  // 16 halves = 32 bytes
      unsigned ah[4][4], al[4][4], bh[4][2], bl[4][2];
#pragma unroll
      for (int mt = 0; mt < 4; mt++) {
        unsigned rowb = (unsigned)((wm * 64 + mt * 16) * GKP * 2);
        ldm4(base + SA_HI_B + rowb + aoff + kadd, ah[mt]);
        ldm4(base + SA_LO_B + rowb + aoff + kadd, al[mt]);
      }
#pragma unroll
      for (int nt = 0; nt < 4; nt++) {
        unsigned rowb = (unsigned)((wn * 32 + nt * 8) * GKP * 2);
        ldm2(base + SB_HI_B + rowb + boff + kadd, bh[nt]);
        ldm2(base + SB_LO_B + rowb + boff + kadd, bl[nt]);
      }
#pragma unroll
      for (int mt = 0; mt < 4; mt++)
#pragma unroll
        for (int nt = 0; nt < 4; nt++) mma16816(acc[mt][nt], ah[mt], bh[nt]);
#pragma unroll
      for (int mt = 0; mt < 4; mt++)
#pragma unroll
        for (int nt = 0; nt < 4; nt++) mma16816(acc[mt][nt], al[mt], bh[nt]);
#pragma unroll
      for (int mt = 0; mt < 4; mt++)
#pragma unroll
        for (int nt = 0; nt < 4; nt++) mma16816(acc[mt][nt], ah[mt], bl[nt]);
    }
    __syncthreads();
    buf ^= 1;
  }

  // Epilogue: c frag m16n8 -> rows lane/4 (+8), cols (lane%4)*2 (+1)
#pragma unroll
  for (int mt = 0; mt < 4; mt++) {
    const int row = m0 + wm * 64 + mt * 16 + (lane >> 2);
#pragma unroll
    for (int nt = 0; nt < 4; nt++) {
      const int col = n0 + wn * 32 + nt * 8 + (lane & 3) * 2;
      float2 bv = *(const float2*)(bias + col);
      float2 o0 = make_float2(acc[mt][nt][0] + bv.x, acc[mt][nt][1] + bv.y);
      float2 o1 = make_float2(acc[mt][nt][2] + bv.x, acc[mt][nt][3] + bv.y);
      *(float2*)(Y + (size_t)row * N_TOT + col) = o0;
      *(float2*)(Y + (size_t)(row + 8) * N_TOT + col) = o1;
    }
  }
}

// ---------------------------------------------------------------------------
// Fused flash attention (SIMT fp32).  Changes vs R1: Qs rows padded to 132 so
// the 8 a-values load as 2x LDS.128, and P stored TRANSPOSED (Ps[k][q], row
// 132) so PV's 8 p-values load as 2x LDS.128.  12 -> 6 LDS per 32 FMA.
// ---------------------------------------------------------------------------
#define TQ 128
#define TK 64
#define QS_RL 132
#define KS_RL 65
#define VS_RL 68
#define PS_RL 132
#define QS_OFF 0
#define KS_OFF (64 * QS_RL)                  // 8448
#define VS_OFF (KS_OFF + 64 * KS_RL)         // 12608
#define PS_OFF (VS_OFF + 64 * VS_RL)         // 16960
#define MB_OFF (PS_OFF + TK * PS_RL)         // 25408
#define ATTN_SMEM_FLOATS (MB_OFF + TK)       // 25472
#define ATTN_SMEM_BYTES (ATTN_SMEM_FLOATS * 4)

__global__ __launch_bounds__(256, 2) void attn_kernel(
    const float* __restrict__ Qp, const float* __restrict__ Kp,
    const float* __restrict__ Vp, const unsigned* __restrict__ mask,
    const unsigned* __restrict__ semask, float* __restrict__ Out) {
  extern __shared__ float sm[];

  const int tid = threadIdx.x;
  const int tx = tid & 15;
  const int ty = tid >> 4;
  const int b = blockIdx.z;
  const int h = blockIdx.y;
  const int q0 = blockIdx.x * TQ;
  const size_t hb = ((size_t)b * S_) * D_ + (size_t)h * DH_;

  // Load Q tile transposed: Qs[d][q]
  {
    const int q = tid >> 1;
    const int d0 = (tid & 1) * 32;
    const float* src = Qp + hb + (size_t)(q0 + q) * D_ + d0;
#pragma unroll
    for (int c = 0; c < 32; c += 4) {
      float4 t = *(const float4*)(src + c);
      sm[QS_OFF + (d0 + c + 0) * QS_RL + q] = t.x;
      sm[QS_OFF + (d0 + c + 1) * QS_RL + q] = t.y;
      sm[QS_OFF + (d0 + c + 2) * QS_RL + q] = t.z;
      sm[QS_OFF + (d0 + c + 3) * QS_RL + q] = t.w;
    }
  }

  float m_i[8], l_i[8], O[8][4];
#pragma unroll
  for (int i = 0; i < 8; i++) {
    m_i[i] = -1e30f;
    l_i[i] = 0.f;
#pragma unroll
    for (int j = 0; j < 4; j++) O[i][j] = 0.f;
  }

  const unsigned* mk = mask + (size_t)b * S_;
  const unsigned* smk = semask + (size_t)b * S_;
  const float scale = 0.125f;  // 1/sqrt(64)

  for (int kt = 0; kt < S_; kt += TK) {
    __syncthreads();
    // Load K (transposed) + V + mask flags
    {
      const int k = tid >> 2;
      const int d0 = (tid & 3) * 16;
      const float* ksrc = Kp + hb + (size_t)(kt + k) * D_ + d0;
      const float* vsrc = Vp + hb + (size_t)(kt + k) * D_ + d0;
#pragma unroll
      for (int c = 0; c < 16; c += 4) {
        float4 t = *(const float4*)(ksrc + c);
        sm[KS_OFF + (d0 + c + 0) * KS_RL + k] = t.x;
        sm[KS_OFF + (d0 + c + 1) * KS_RL + k] = t.y;
        sm[KS_OFF + (d0 + c + 2) * KS_RL + k] = t.z;
        sm[KS_OFF + (d0 + c + 3) * KS_RL + k] = t.w;
        float4 u = *(const float4*)(vsrc + c);
        *(float4*)&sm[VS_OFF + k * VS_RL + d0 + c] = u;
      }
      if (tid < TK) {
        sm[MB_OFF + tid] = (mk[kt + tid] | smk[kt + tid]) ? 1.0f : 0.0f;
      }
    }
    __syncthreads();

    // S = Q K^T (fp32)
    float Sf[8][4];
#pragma unroll
    for (int i = 0; i < 8; i++)
#pragma unroll
      for (int j = 0; j < 4; j++) Sf[i][j] = 0.f;

#pragma unroll 8
    for (int d = 0; d < DH_; d++) {
      float4 a0 = *(const float4*)&sm[QS_OFF + d * QS_RL + ty * 8];
      float4 a1 = *(const float4*)&sm[QS_OFF + d * QS_RL + ty * 8 + 4];
      float a[8] = {a0.x, a0.y, a0.z, a0.w, a1.x, a1.y, a1.z, a1.w};
      float bb[4];
#pragma unroll
      for (int j = 0; j < 4; j++) bb[j] = sm[KS_OFF + d * KS_RL + tx + 16 * j];
#pragma unroll
      for (int i = 0; i < 8; i++)
#pragma unroll
        for (int j = 0; j < 4; j++) Sf[i][j] = fmaf(a[i], bb[j], Sf[i][j]);
    }

    // scale + mask (exactly -1e9, matching reference)
    float mbv[4];
#pragma unroll
    for (int j = 0; j < 4; j++) mbv[j] = sm[MB_OFF + tx + 16 * j];
#pragma unroll
    for (int i = 0; i < 8; i++)
#pragma unroll
      for (int j = 0; j < 4; j++) {
        float s = Sf[i][j] * scale;
        Sf[i][j] = (mbv[j] != 0.f) ? -1e9f : s;
      }

    // Online softmax update + store P transposed (Ps[k][q])
#pragma unroll
    for (int i = 0; i < 8; i++) {
      float rm = fmaxf(fmaxf(Sf[i][0], Sf[i][1]), fmaxf(Sf[i][2], Sf[i][3]));
#pragma unroll
      for (int off = 8; off > 0; off >>= 1)
        rm = fmaxf(rm, __shfl_xor_sync(0xffffffffu, rm, off));
      const float mn = fmaxf(m_i[i], rm);
      float p[4];
      float rs = 0.f;
#pragma unroll
      for (int j = 0; j < 4; j++) {
        p[j] = __expf(Sf[i][j] - mn);
        rs += p[j];
      }
#pragma unroll
      for (int off = 8; off > 0; off >>= 1)
        rs += __shfl_xor_sync(0xffffffffu, rs, off);
      const float alpha = __expf(m_i[i] - mn);
      l_i[i] = l_i[i] * alpha + rs;
      m_i[i] = mn;
#pragma unroll
      for (int j = 0; j < 4; j++) {
        O[i][j] *= alpha;
        sm[PS_OFF + (tx + 16 * j) * PS_RL + ty * 8 + i] = p[j];
      }
    }
    __syncthreads();

    // O += P @ V   (p: 2x LDS.128 from transposed Ps)
#pragma unroll 4
    for (int kk = 0; kk < TK; kk++) {
      float4 p0 = *(const float4*)&sm[PS_OFF + kk * PS_RL + ty * 8];
      float4 p1 = *(const float4*)&sm[PS_OFF + kk * PS_RL + ty * 8 + 4];
      float p[8] = {p0.x, p0.y, p0.z, p0.w, p1.x, p1.y, p1.z, p1.w};
      float v[4];
#pragma unroll
      for (int j = 0; j < 4; j++) v[j] = sm[VS_OFF + kk * VS_RL + tx + 16 * j];
#pragma unroll
      for (int i = 0; i < 8; i++)
#pragma unroll
        for (int j = 0; j < 4; j++) O[i][j] = fmaf(p[i], v[j], O[i][j]);
    }
  }

  // Epilogue: normalize and write merged-head layout
#pragma unroll
  for (int i = 0; i < 8; i++) {
    const float inv = 1.f / l_i[i];
    float* op = Out + hb + (size_t)(q0 + ty * 8 + i) * D_;
#pragma unroll
    for (int j = 0; j < 4; j++) op[tx + 16 * j] = O[i][j] * inv;
  }
}

// ---------------------------------------------------------------------------
// Launch
// ---------------------------------------------------------------------------
extern "C" void kernel_launch(void* const* d_in, const int* in_sizes, int n_in,
                              void* d_out, int out_size) {
  const float* v = (const float*)d_in[0];
  const float* k = (const float*)d_in[1];
  const float* q = (const float*)d_in[2];
  const unsigned* mask = (const unsigned*)d_in[3];
  const unsigned* semask = (const unsigned*)d_in[4];
  const float* Wv = (const float*)d_in[5];
  const float* bv = (const float*)d_in[6];
  const float* Wk = (const float*)d_in[7];
  const float* bk = (const float*)d_in[8];
  const float* Wq = (const float*)d_in[9];
  const float* bq = (const float*)d_in[10];
  const float* Wm = (const float*)d_in[11];
  const float* bm = (const float*)d_in[12];
  float* out = (float*)d_out;

  float *gq, *gk, *gv, *ga;
  __nv_bfloat16 *xhi, *xlo, *whi, *wlo;
  cudaGetSymbolAddress((void**)&gq, g_q);
  cudaGetSymbolAddress((void**)&gk, g_k);
  cudaGetSymbolAddress((void**)&gv, g_v);
  cudaGetSymbolAddress((void**)&ga, g_att);
  cudaGetSymbolAddress((void**)&xhi, g_xhi);
  cudaGetSymbolAddress((void**)&xlo, g_xlo);
  cudaGetSymbolAddress((void**)&whi, g_whi);
  cudaGetSymbolAddress((void**)&wlo, g_wlo);

  cudaFuncSetAttribute(attn_kernel, cudaFuncAttributeMaxDynamicSharedMemorySize,
                       ATTN_SMEM_BYTES);
  cudaFuncSetAttribute(gemm_mma_kernel,
                       cudaFuncAttributeMaxDynamicSharedMemorySize,
                       GEMM_SMEM_BYTES);

  const int nx4 = M_TOT * K_TOT / 4;  // input tensors, float4 count
  const int nw4 = N_TOT * K_TOT / 4;  // weight tensors
  const dim3 cblk(256);
  const dim3 cgx((nx4 + 255) / 256);
  const dim3 cgw((nw4 + 255) / 256);
  const dim3 ggrid(N_TOT / 128, M_TOT / 128);  // (8, 32)
  const dim3 gblk(256);

#define RUN_GEMM(XPTR, WPTR, BPTR, YPTR)                                      \
  cvt_split_kernel<<<cgx, cblk>>>((const float4*)(XPTR), (__nv_bfloat162*)xhi, \
                                  (__nv_bfloat162*)xlo, nx4);                  \
  cvt_split_kernel<<<cgw, cblk>>>((const float4*)(WPTR), (__nv_bfloat162*)whi, \
                                  (__nv_bfloat162*)wlo, nw4);                  \
  gemm_mma_kernel<<<ggrid, gblk, GEMM_SMEM_BYTES>>>(xhi, xlo, whi, wlo,        \
                                                    (BPTR), (YPTR));

  RUN_GEMM(v, Wv, bv, gv)
  RUN_GEMM(k, Wk, bk, gk)
  RUN_GEMM(q, Wq, bq, gq)

  attn_kernel<<<dim3(S_ / TQ, H_, B_), dim3(256), ATTN_SMEM_BYTES>>>(
      gq, gk, gv, mask, semask, ga);

  RUN_GEMM(ga, Wm, bm, out)
}

// round 3
// speedup vs baseline: 2.1639x; 1.4964x over previous
#include <cuda_runtime.h>
#include <cuda_bf16.h>

// Problem constants
#define B_ 4
#define S_ 1024
#define D_ 1024
#define H_ 16
#define DH_ 64
#define M_TOT (B_ * S_)   // 4096
#define N_TOT D_          // 1024
#define K_TOT D_          // 1024

// Scratch (allocation-free rule: __device__ globals)
__device__ __nv_bfloat16 g_xhi[M_TOT * K_TOT];
__device__ __nv_bfloat16 g_xlo[M_TOT * K_TOT];
__device__ __nv_bfloat16 g_whi[N_TOT * K_TOT];
__device__ __nv_bfloat16 g_wlo[N_TOT * K_TOT];
// projection outputs (bf16 hi/lo)
__device__ __nv_bfloat16 g_qh[M_TOT * D_];
__device__ __nv_bfloat16 g_ql[M_TOT * D_];
__device__ __nv_bfloat16 g_kh[M_TOT * D_];
__device__ __nv_bfloat16 g_kl[M_TOT * D_];
__device__ __nv_bfloat16 g_vh[M_TOT * D_];
__device__ __nv_bfloat16 g_vl[M_TOT * D_];
// attention output (bf16 hi/lo)
__device__ __nv_bfloat16 g_ah[M_TOT * D_];
__device__ __nv_bfloat16 g_al[M_TOT * D_];

// ---------------------------------------------------------------------------
// helpers
// ---------------------------------------------------------------------------
__device__ __forceinline__ void cp16(unsigned dst, const void* src) {
  asm volatile("cp.async.cg.shared.global [%0], [%1], 16;\n" ::"r"(dst),
               "l"(src));
}
__device__ __forceinline__ void ldm4(unsigned addr, unsigned* r) {
  asm volatile("ldmatrix.sync.aligned.m8n8.x4.shared.b16 {%0,%1,%2,%3}, [%4];"
               : "=r"(r[0]), "=r"(r[1]), "=r"(r[2]), "=r"(r[3])
               : "r"(addr));
}
__device__ __forceinline__ void ldm2(unsigned addr, unsigned* r) {
  asm volatile("ldmatrix.sync.aligned.m8n8.x2.shared.b16 {%0,%1}, [%2];"
               : "=r"(r[0]), "=r"(r[1])
               : "r"(addr));
}
__device__ __forceinline__ void ldm2t(unsigned addr, unsigned* r) {
  asm volatile(
      "ldmatrix.sync.aligned.m8n8.x2.trans.shared.b16 {%0,%1}, [%2];"
      : "=r"(r[0]), "=r"(r[1])
      : "r"(addr));
}
__device__ __forceinline__ void mma16816(float* c, const unsigned* a,
                                         const unsigned* b) {
  asm volatile(
      "mma.sync.aligned.m16n8k16.row.col.f32.bf16.bf16.f32 "
      "{%0,%1,%2,%3},{%4,%5,%6,%7},{%8,%9},{%0,%1,%2,%3};"
      : "+f"(c[0]), "+f"(c[1]), "+f"(c[2]), "+f"(c[3])
      : "r"(a[0]), "r"(a[1]), "r"(a[2]), "r"(a[3]), "r"(b[0]), "r"(b[1]));
}
// split x0,x1 into bf16 hi (ret) / lo (out param), packed as bf16x2 words
__device__ __forceinline__ unsigned split2(float x0, float x1, unsigned& lo) {
  __nv_bfloat16 h0 = __float2bfloat16(x0);
  __nv_bfloat16 h1 = __float2bfloat16(x1);
  __nv_bfloat16 l0 = __float2bfloat16(x0 - __bfloat162float(h0));
  __nv_bfloat16 l1 = __float2bfloat16(x1 - __bfloat162float(h1));
  __nv_bfloat162 tl = __halves2bfloat162(l0, l1);
  lo = *reinterpret_cast<unsigned*>(&tl);
  __nv_bfloat162 th = __halves2bfloat162(h0, h1);
  return *reinterpret_cast<unsigned*>(&th);
}

// ---------------------------------------------------------------------------
// fp32 -> (bf16 hi, bf16 lo) split conversion.
// ---------------------------------------------------------------------------
__global__ __launch_bounds__(256) void cvt_split_kernel(
    const float4* __restrict__ x, __nv_bfloat162* __restrict__ hi,
    __nv_bfloat162* __restrict__ lo, int n4) {
  int i = blockIdx.x * blockDim.x + threadIdx.x;
  if (i >= n4) return;
  float4 t = x[i];
  unsigned l0, l1;
  unsigned h0 = split2(t.x, t.y, l0);
  unsigned h1 = split2(t.z, t.w, l1);
  *(unsigned*)&hi[i * 2 + 0] = h0;
  *(unsigned*)&hi[i * 2 + 1] = h1;
  *(unsigned*)&lo[i * 2 + 0] = l0;
  *(unsigned*)&lo[i * 2 + 1] = l1;
}

// ---------------------------------------------------------------------------
// Tensor-core GEMM: Y[M,N] = X[M,K] @ W[N,K]^T + bias, X/W as bf16 hi/lo.
// acc = Xhi*Whi + Xhi*Wlo + Xlo*Whi.  SPLIT epilogue writes bf16 hi/lo.
// ---------------------------------------------------------------------------
#define GKP 40
#define SA_HI_B 0
#define SA_LO_B (128 * GKP * 2)
#define SB_HI_B (2 * 128 * GKP * 2)
#define SB_LO_B (3 * 128 * GKP * 2)
#define GBUF_B (4 * 128 * GKP * 2)
#define GEMM_SMEM_BYTES (2 * GBUF_B)

template <bool SPLIT>
__global__ __launch_bounds__(256, 1) void gemm_mma_kernel(
    const __nv_bfloat16* __restrict__ Ahi, const __nv_bfloat16* __restrict__ Alo,
    const __nv_bfloat16* __restrict__ Bhi, const __nv_bfloat16* __restrict__ Blo,
    const float* __restrict__ bias, float* __restrict__ Y,
    __nv_bfloat16* __restrict__ Yhi, __nv_bfloat16* __restrict__ Ylo) {
  extern __shared__ __nv_bfloat16 sh[];
  const int tid = threadIdx.x;
  const int lane = tid & 31;
  const int warp = tid >> 5;
  const int wm = warp >> 2;
  const int wn = warp & 3;
  const int m0 = blockIdx.y * 128;
  const int n0 = blockIdx.x * 128;

  const int lrow = tid >> 1;
  const int lcol = (tid & 1) * 16;

  const unsigned sbase = (unsigned)__cvta_generic_to_shared(sh);
  const unsigned sdst = sbase + (unsigned)(lrow * GKP + lcol) * 2;

  const __nv_bfloat16* gAh = Ahi + (size_t)(m0 + lrow) * K_TOT + lcol;
  const __nv_bfloat16* gAl = Alo + (size_t)(m0 + lrow) * K_TOT + lcol;
  const __nv_bfloat16* gBh = Bhi + (size_t)(n0 + lrow) * K_TOT + lcol;
  const __nv_bfloat16* gBl = Blo + (size_t)(n0 + lrow) * K_TOT + lcol;

  float acc[4][4][4];
#pragma unroll
  for (int i = 0; i < 4; i++)
#pragma unroll
    for (int j = 0; j < 4; j++)
#pragma unroll
      for (int c = 0; c < 4; c++) acc[i][j][c] = 0.f;

  const unsigned aoff = (unsigned)(((lane & 15) * GKP + ((lane >> 4) & 1) * 8) * 2);
  const unsigned boff = (unsigned)(((lane & 7) * GKP + ((lane >> 3) & 1) * 8) * 2);

#define GEMM_ISSUE(k0, buf)                   \
  {                                           \
    unsigned d = sdst + (buf) * GBUF_B;       \
    cp16(d + SA_HI_B, gAh + (k0));            \
    cp16(d + SA_HI_B + 16, gAh + (k0) + 8);   \
    cp16(d + SA_LO_B, gAl + (k0));            \
    cp16(d + SA_LO_B + 16, gAl + (k0) + 8);   \
    cp16(d + SB_HI_B, gBh + (k0));            \
    cp16(d + SB_HI_B + 16, gBh + (k0) + 8);   \
    cp16(d + SB_LO_B, gBl + (k0));            \
    cp16(d + SB_LO_B + 16, gBl + (k0) + 8);   \
    asm volatile("cp.async.commit_group;\n"); \
  }

  GEMM_ISSUE(0, 0)

  const int NCHUNK = K_TOT / 32;
  int buf = 0;
  for (int t = 0; t < NCHUNK; t++) {
    if (t + 1 < NCHUNK) {
      GEMM_ISSUE((t + 1) * 32, buf ^ 1)
      asm volatile("cp.async.wait_group 1;\n");
    } else {
      asm volatile("cp.async.wait_group 0;\n");
    }
    __syncthreads();

    const unsigned base = sbase + buf * GBUF_B;
#pragma unroll
    for (int kk = 0; kk < 2; kk++) {
      const unsigned kadd = kk * 32;
      unsigned ah[4][4], al[4][4], bh[4][2], bl[4][2];
#pragma unroll
      for (int mt = 0; mt < 4; mt++) {
        unsigned rowb = (unsigned)((wm * 64 + mt * 16) * GKP * 2);
        ldm4(base + SA_HI_B + rowb + aoff + kadd, ah[mt]);
        ldm4(base + SA_LO_B + rowb + aoff + kadd, al[mt]);
      }
#pragma unroll
      for (int nt = 0; nt < 4; nt++) {
        unsigned rowb = (unsigned)((wn * 32 + nt * 8) * GKP * 2);
        ldm2(base + SB_HI_B + rowb + boff + kadd, bh[nt]);
        ldm2(base + SB_LO_B + rowb + boff + kadd, bl[nt]);
      }
#pragma unroll
      for (int mt = 0; mt < 4; mt++)
#pragma unroll
        for (int nt = 0; nt < 4; nt++) mma16816(acc[mt][nt], ah[mt], bh[nt]);
#pragma unroll
      for (int mt = 0; mt < 4; mt++)
#pragma unroll
        for (int nt = 0; nt < 4; nt++) mma16816(acc[mt][nt], al[mt], bh[nt]);
#pragma unroll
      for (int mt = 0; mt < 4; mt++)
#pragma unroll
        for (int nt = 0; nt < 4; nt++) mma16816(acc[mt][nt], ah[mt], bl[nt]);
    }
    __syncthreads();
    buf ^= 1;
  }

#pragma unroll
  for (int mt = 0; mt < 4; mt++) {
    const int row = m0 + wm * 64 + mt * 16 + (lane >> 2);
#pragma unroll
    for (int nt = 0; nt < 4; nt++) {
      const int col = n0 + wn * 32 + nt * 8 + (lane & 3) * 2;
      float2 bv = *(const float2*)(bias + col);
      float v0 = acc[mt][nt][0] + bv.x;
      float v1 = acc[mt][nt][1] + bv.y;
      float v2 = acc[mt][nt][2] + bv.x;
      float v3 = acc[mt][nt][3] + bv.y;
      if (SPLIT) {
        unsigned lo0, lo1;
        unsigned hi0 = split2(v0, v1, lo0);
        unsigned hi1 = split2(v2, v3, lo1);
        *(unsigned*)&Yhi[(size_t)row * N_TOT + col] = hi0;
        *(unsigned*)&Ylo[(size_t)row * N_TOT + col] = lo0;
        *(unsigned*)&Yhi[(size_t)(row + 8) * N_TOT + col] = hi1;
        *(unsigned*)&Ylo[(size_t)(row + 8) * N_TOT + col] = lo1;
      } else {
        *(float2*)(Y + (size_t)row * N_TOT + col) = make_float2(v0, v1);
        *(float2*)(Y + (size_t)(row + 8) * N_TOT + col) = make_float2(v2, v3);
      }
    }
  }
}

// ---------------------------------------------------------------------------
// Tensor-core flash attention (bf16 hi/lo split, fp32 softmax).
// Block = (b, h, 128-q tile).  8 warps, warp = 16 q rows x 64 kseq/d cols.
// K/V tiles of 64, cp.async double-buffered.
// ---------------------------------------------------------------------------
#define ARL 72  // padded halves per smem row (144B -> conflict-free ldmatrix)
// half-offsets inside dynamic smem
#define AQH 0
#define AQL (128 * ARL)                 // 9216
#define AKV0 (2 * 128 * ARL)            // 18432
#define KV_STRIDE (4 * 64 * ARL)        // 18432 halves per stage
#define KH_OFF 0
#define KL_OFF (64 * ARL)               // 4608
#define VH_OFF (2 * 64 * ARL)           // 9216
#define VL_OFF (3 * 64 * ARL)           // 13824
#define AMASK_H (AKV0 + 2 * KV_STRIDE)  // 55296 halves
#define ATTN_SMEM_BYTES (AMASK_H * 2 + 2 * 64 * 4)  // 111104

__global__ __launch_bounds__(256, 1) void attn_mma_kernel(
    const __nv_bfloat16* __restrict__ qhi, const __nv_bfloat16* __restrict__ qlo,
    const __nv_bfloat16* __restrict__ khi, const __nv_bfloat16* __restrict__ klo,
    const __nv_bfloat16* __restrict__ vhi, const __nv_bfloat16* __restrict__ vlo,
    const unsigned* __restrict__ mask, const unsigned* __restrict__ semask,
    __nv_bfloat16* __restrict__ ohi, __nv_bfloat16* __restrict__ olo) {
  extern __shared__ __nv_bfloat16 sb[];
  float* mflag = (float*)(sb + AMASK_H);

  const int tid = threadIdx.x;
  const int lane = tid & 31;
  const int warp = tid >> 5;
  const int b = blockIdx.z;
  const int h = blockIdx.y;
  const int q0 = blockIdx.x * 128;
  const size_t qbase = ((size_t)(b * S_ + q0)) * D_ + h * DH_;
  const size_t kbase = ((size_t)(b * S_)) * D_ + h * DH_;
  const unsigned sbB = (unsigned)__cvta_generic_to_shared(sb);
  const unsigned* mk = mask + (size_t)b * S_;
  const unsigned* smk = semask + (size_t)b * S_;

#define ISSUE_KV(kt, st)                                                     \
  {                                                                          \
    _Pragma("unroll") for (int r = 0; r < 2; r++) {                          \
      int idx = tid + 256 * r;                                               \
      int row = idx >> 3, ch = idx & 7;                                      \
      unsigned d = sbB +                                                     \
          (unsigned)((AKV0 + (st)*KV_STRIDE + row * ARL + ch * 8) * 2);      \
      size_t go = kbase + (size_t)((kt) + row) * D_ + ch * 8;                \
      cp16(d + KH_OFF * 2, khi + go);                                        \
      cp16(d + KL_OFF * 2, klo + go);                                        \
      cp16(d + VH_OFF * 2, vhi + go);                                        \
      cp16(d + VL_OFF * 2, vlo + go);                                        \
    }                                                                        \
  }

  // Prologue: Q tile + KV tile 0 + mask 0
#pragma unroll
  for (int r = 0; r < 4; r++) {
    int idx = tid + 256 * r;
    int row = idx >> 3, ch = idx & 7;
    unsigned d = sbB + (unsigned)((row * ARL + ch * 8) * 2);
    size_t go = qbase + (size_t)row * D_ + ch * 8;
    cp16(d + AQH * 2, qhi + go);
    cp16(d + AQL * 2, qlo + go);
  }
  ISSUE_KV(0, 0)
  if (tid < 64) mflag[tid] = (mk[tid] | smk[tid]) ? 1.0f : 0.0f;
  asm volatile("cp.async.commit_group;\n");
  asm volatile("cp.async.wait_group 0;\n");
  __syncthreads();

  // Q fragments (A operand, m16k16, per d-chunk) — held in registers
  unsigned qh[4][4], ql[4][4];
  {
    const unsigned arow =
        (unsigned)(((warp * 16 + (lane & 15)) * ARL + ((lane >> 4) & 1) * 8) * 2);
#pragma unroll
    for (int kc = 0; kc < 4; kc++) {
      ldm4(sbB + AQH * 2 + arow + kc * 32, qh[kc]);
      ldm4(sbB + AQL * 2 + arow + kc * 32, ql[kc]);
    }
  }

  float m_i[2] = {-1e30f, -1e30f};
  float l_i[2] = {0.f, 0.f};
  float O[8][4];
#pragma unroll
  for (int nt = 0; nt < 8; nt++)
#pragma unroll
    for (int c = 0; c < 4; c++) O[nt][c] = 0.f;

  int st = 0;
  for (int t = 0; t < S_ / 64; t++) {
    const int kt = t * 64;
    if (t + 1 < S_ / 64) {
      ISSUE_KV(kt + 64, st ^ 1)
      if (tid < 64)
        mflag[(st ^ 1) * 64 + tid] =
            (mk[kt + 64 + tid] | smk[kt + 64 + tid]) ? 1.0f : 0.0f;
      asm volatile("cp.async.commit_group;\n");
    }

    const unsigned kb = sbB + (unsigned)((AKV0 + st * KV_STRIDE) * 2);

    // ---- S = Q K^T (3-term split) ----
    float S[8][4];
#pragma unroll
    for (int nt = 0; nt < 8; nt++)
#pragma unroll
      for (int c = 0; c < 4; c++) S[nt][c] = 0.f;

#pragma unroll
    for (int kc = 0; kc < 4; kc++) {
#pragma unroll
      for (int nt = 0; nt < 8; nt++) {
        unsigned baddr = kb +
            (unsigned)(((nt * 8 + (lane & 7)) * ARL + kc * 16 +
                        ((lane >> 3) & 1) * 8) * 2);
        unsigned bh[2], bl[2];
        ldm2(baddr + KH_OFF * 2, bh);
        ldm2(baddr + KL_OFF * 2, bl);
        mma16816(S[nt], qh[kc], bh);
        mma16816(S[nt], qh[kc], bl);
        mma16816(S[nt], ql[kc], bh);
      }
    }

    // ---- scale + mask + online softmax ----
    const float* mf = mflag + st * 64;
    float rm0 = -1e30f, rm1 = -1e30f;
    float2 fl[8];
#pragma unroll
    for (int nt = 0; nt < 8; nt++) {
      fl[nt] = *(const float2*)&mf[nt * 8 + (lane & 3) * 2];
      float s0 = S[nt][0] * 0.125f;
      float s1 = S[nt][1] * 0.125f;
      float s2 = S[nt][2] * 0.125f;
      float s3 = S[nt][3] * 0.125f;
      s0 = (fl[nt].x != 0.f) ? -1e9f : s0;
      s1 = (fl[nt].y != 0.f) ? -1e9f : s1;
      s2 = (fl[nt].x != 0.f) ? -1e9f : s2;
      s3 = (fl[nt].y != 0.f) ? -1e9f : s3;
      S[nt][0] = s0; S[nt][1] = s1; S[nt][2] = s2; S[nt][3] = s3;
      rm0 = fmaxf(rm0, fmaxf(s0, s1));
      rm1 = fmaxf(rm1, fmaxf(s2, s3));
    }
    rm0 = fmaxf(rm0, __shfl_xor_sync(0xffffffffu, rm0, 1));
    rm0 = fmaxf(rm0, __shfl_xor_sync(0xffffffffu, rm0, 2));
    rm1 = fmaxf(rm1, __shfl_xor_sync(0xffffffffu, rm1, 1));
    rm1 = fmaxf(rm1, __shfl_xor_sync(0xffffffffu, rm1, 2));

    const float mn0 = fmaxf(m_i[0], rm0);
    const float mn1 = fmaxf(m_i[1], rm1);
    const float a0 = __expf(m_i[0] - mn0);
    const float a1 = __expf(m_i[1] - mn1);
    float rs0 = 0.f, rs1 = 0.f;
#pragma unroll
    for (int nt = 0; nt < 8; nt++) {
      S[nt][0] = __expf(S[nt][0] - mn0);
      S[nt][1] = __expf(S[nt][1] - mn0);
      S[nt][2] = __expf(S[nt][2] - mn1);
      S[nt][3] = __expf(S[nt][3] - mn1);
      rs0 += S[nt][0] + S[nt][1];
      rs1 += S[nt][2] + S[nt][3];
    }
    rs0 += __shfl_xor_sync(0xffffffffu, rs0, 1);
    rs0 += __shfl_xor_sync(0xffffffffu, rs0, 2);
    rs1 += __shfl_xor_sync(0xffffffffu, rs1, 1);
    rs1 += __shfl_xor_sync(0xffffffffu, rs1, 2);
    l_i[0] = l_i[0] * a0 + rs0;
    l_i[1] = l_i[1] * a1 + rs1;
    m_i[0] = mn0;
    m_i[1] = mn1;
#pragma unroll
    for (int nt = 0; nt < 8; nt++) {
      O[nt][0] *= a0;
      O[nt][1] *= a0;
      O[nt][2] *= a1;
      O[nt][3] *= a1;
    }

    // ---- O += P V (3-term split, P from S frags in registers) ----
#pragma unroll
    for (int kc2 = 0; kc2 < 4; kc2++) {
      unsigned pa_h[4], pa_l[4];
      pa_h[0] = split2(S[2 * kc2][0], S[2 * kc2][1], pa_l[0]);
      pa_h[1] = split2(S[2 * kc2][2], S[2 * kc2][3], pa_l[1]);
      pa_h[2] = split2(S[2 * kc2 + 1][0], S[2 * kc2 + 1][1], pa_l[2]);
      pa_h[3] = split2(S[2 * kc2 + 1][2], S[2 * kc2 + 1][3], pa_l[3]);
#pragma unroll
      for (int nt2 = 0; nt2 < 8; nt2++) {
        unsigned vaddr = kb +
            (unsigned)(((kc2 * 16 + (lane & 15)) * ARL + nt2 * 8) * 2);
        unsigned vh2[2], vl2[2];
        ldm2t(vaddr + VH_OFF * 2, vh2);
        ldm2t(vaddr + VL_OFF * 2, vl2);
        mma16816(O[nt2], pa_h, vh2);
        mma16816(O[nt2], pa_h, vl2);
        mma16816(O[nt2], pa_l, vh2);
      }
    }

    if (t + 1 < S_ / 64) {
      asm volatile("cp.async.wait_group 0;\n");
      __syncthreads();
      st ^= 1;
    }
  }

  // ---- epilogue: normalize, split hi/lo, write merged-head layout ----
  const float inv0 = 1.f / l_i[0];
  const float inv1 = 1.f / l_i[1];
  const int r0 = q0 + warp * 16 + (lane >> 2);
  const int colb = h * DH_ + (lane & 3) * 2;
#pragma unroll
  for (int nt = 0; nt < 8; nt++) {
    const int col = colb + nt * 8;
    unsigned lo0, lo1;
    unsigned hi0 = split2(O[nt][0] * inv0, O[nt][1] * inv0, lo0);
    unsigned hi1 = split2(O[nt][2] * inv1, O[nt][3] * inv1, lo1);
    *(unsigned*)&ohi[(size_t)(b * S_ + r0) * D_ + col] = hi0;
    *(unsigned*)&olo[(size_t)(b * S_ + r0) * D_ + col] = lo0;
    *(unsigned*)&ohi[(size_t)(b * S_ + r0 + 8) * D_ + col] = hi1;
    *(unsigned*)&olo[(size_t)(b * S_ + r0 + 8) * D_ + col] = lo1;
  }
}

// ---------------------------------------------------------------------------
// Launch
// ---------------------------------------------------------------------------
extern "C" void kernel_launch(void* const* d_in, const int* in_sizes, int n_in,
                              void* d_out, int out_size) {
  const float* v = (const float*)d_in[0];
  const float* k = (const float*)d_in[1];
  const float* q = (const float*)d_in[2];
  const unsigned* mask = (const unsigned*)d_in[3];
  const unsigned* semask = (const unsigned*)d_in[4];
  const float* Wv = (const float*)d_in[5];
  const float* bv = (const float*)d_in[6];
  const float* Wk = (const float*)d_in[7];
  const float* bk = (const float*)d_in[8];
  const float* Wq = (const float*)d_in[9];
  const float* bq = (const float*)d_in[10];
  const float* Wm = (const float*)d_in[11];
  const float* bm = (const float*)d_in[12];
  float* out = (float*)d_out;

  __nv_bfloat16 *xhi, *xlo, *whi, *wlo;
  __nv_bfloat16 *qh, *ql, *kh, *kl, *vh, *vl, *ah, *al;
  cudaGetSymbolAddress((void**)&xhi, g_xhi);
  cudaGetSymbolAddress((void**)&xlo, g_xlo);
  cudaGetSymbolAddress((void**)&whi, g_whi);
  cudaGetSymbolAddress((void**)&wlo, g_wlo);
  cudaGetSymbolAddress((void**)&qh, g_qh);
  cudaGetSymbolAddress((void**)&ql, g_ql);
  cudaGetSymbolAddress((void**)&kh, g_kh);
  cudaGetSymbolAddress((void**)&kl, g_kl);
  cudaGetSymbolAddress((void**)&vh, g_vh);
  cudaGetSymbolAddress((void**)&vl, g_vl);
  cudaGetSymbolAddress((void**)&ah, g_ah);
  cudaGetSymbolAddress((void**)&al, g_al);

  cudaFuncSetAttribute(attn_mma_kernel,
                       cudaFuncAttributeMaxDynamicSharedMemorySize,
                       ATTN_SMEM_BYTES);
  cudaFuncSetAttribute(gemm_mma_kernel<true>,
                       cudaFuncAttributeMaxDynamicSharedMemorySize,
                       GEMM_SMEM_BYTES);
  cudaFuncSetAttribute(gemm_mma_kernel<false>,
                       cudaFuncAttributeMaxDynamicSharedMemorySize,
                       GEMM_SMEM_BYTES);

  const int nx4 = M_TOT * K_TOT / 4;
  const int nw4 = N_TOT * K_TOT / 4;
  const dim3 cblk(256);
  const dim3 cgx((nx4 + 255) / 256);
  const dim3 cgw((nw4 + 255) / 256);
  const dim3 ggrid(N_TOT / 128, M_TOT / 128);
  const dim3 gblk(256);

#define RUN_PROJ(XPTR, WPTR, BPTR, YH, YL)                                     \
  cvt_split_kernel<<<cgx, cblk>>>((const float4*)(XPTR), (__nv_bfloat162*)xhi, \
                                  (__nv_bfloat162*)xlo, nx4);                  \
  cvt_split_kernel<<<cgw, cblk>>>((const float4*)(WPTR), (__nv_bfloat162*)whi, \
                                  (__nv_bfloat162*)wlo, nw4);                  \
  gemm_mma_kernel<true><<<ggrid, gblk, GEMM_SMEM_BYTES>>>(                     \
      xhi, xlo, whi, wlo, (BPTR), nullptr, (YH), (YL));

  RUN_PROJ(v, Wv, bv, vh, vl)
  RUN_PROJ(k, Wk, bk, kh, kl)
  RUN_PROJ(q, Wq, bq, qh, ql)

  attn_mma_kernel<<<dim3(S_ / 128, H_, B_), dim3(256), ATTN_SMEM_BYTES>>>(
      qh, ql, kh, kl, vh, vl, mask, semask, ah, al);

  cvt_split_kernel<<<cgw, cblk>>>((const float4*)Wm, (__nv_bfloat162*)whi,
                                  (__nv_bfloat162*)wlo, nw4);
  gemm_mma_kernel<false><<<ggrid, gblk, GEMM_SMEM_BYTES>>>(
      ah, al, whi, wlo, bm, out, nullptr, nullptr);
}

// round 5
// speedup vs baseline: 2.3238x; 1.0739x over previous
#include <cuda_runtime.h>
#include <cuda_bf16.h>
#include <cstdint>

// Problem constants
#define B_ 4
#define S_ 1024
#define D_ 1024
#define H_ 16
#define DH_ 64
#define M_TOT (B_ * S_)   // 4096
#define N_TOT D_          // 1024
#define K_TOT D_          // 1024

// Scratch (allocation-free rule: __device__ globals)
__device__ __nv_bfloat16 g_xhi[M_TOT * K_TOT];
__device__ __nv_bfloat16 g_xlo[M_TOT * K_TOT];
__device__ __nv_bfloat16 g_whi[N_TOT * K_TOT];
__device__ __nv_bfloat16 g_wlo[N_TOT * K_TOT];
__device__ __nv_bfloat16 g_qh[M_TOT * D_];
__device__ __nv_bfloat16 g_ql[M_TOT * D_];
__device__ __nv_bfloat16 g_kh[M_TOT * D_];
__device__ __nv_bfloat16 g_kl[M_TOT * D_];
__device__ __nv_bfloat16 g_vh[M_TOT * D_];
__device__ __nv_bfloat16 g_vl[M_TOT * D_];
__device__ __nv_bfloat16 g_ah[M_TOT * D_];
__device__ __nv_bfloat16 g_al[M_TOT * D_];

// ---------------------------------------------------------------------------
// helpers
// ---------------------------------------------------------------------------
__device__ __forceinline__ void cp16(unsigned dst, const void* src) {
  asm volatile("cp.async.cg.shared.global [%0], [%1], 16;\n" ::"r"(dst),
               "l"(src));
}
__device__ __forceinline__ void ldm4(unsigned addr, unsigned* r) {
  asm volatile("ldmatrix.sync.aligned.m8n8.x4.shared.b16 {%0,%1,%2,%3}, [%4];"
               : "=r"(r[0]), "=r"(r[1]), "=r"(r[2]), "=r"(r[3])
               : "r"(addr));
}
__device__ __forceinline__ void ldm4t(unsigned addr, unsigned* r) {
  asm volatile(
      "ldmatrix.sync.aligned.m8n8.x4.trans.shared.b16 {%0,%1,%2,%3}, [%4];"
      : "=r"(r[0]), "=r"(r[1]), "=r"(r[2]), "=r"(r[3])
      : "r"(addr));
}
__device__ __forceinline__ void mma16816(float* c, const unsigned* a,
                                         const unsigned* b) {
  asm volatile(
      "mma.sync.aligned.m16n8k16.row.col.f32.bf16.bf16.f32 "
      "{%0,%1,%2,%3},{%4,%5,%6,%7},{%8,%9},{%0,%1,%2,%3};"
      : "+f"(c[0]), "+f"(c[1]), "+f"(c[2]), "+f"(c[3])
      : "r"(a[0]), "r"(a[1]), "r"(a[2]), "r"(a[3]), "r"(b[0]), "r"(b[1]));
}
__device__ __forceinline__ unsigned split2(float x0, float x1, unsigned& lo) {
  __nv_bfloat16 h0 = __float2bfloat16(x0);
  __nv_bfloat16 h1 = __float2bfloat16(x1);
  __nv_bfloat16 l0 = __float2bfloat16(x0 - __bfloat162float(h0));
  __nv_bfloat16 l1 = __float2bfloat16(x1 - __bfloat162float(h1));
  __nv_bfloat162 tl = __halves2bfloat162(l0, l1);
  lo = *reinterpret_cast<unsigned*>(&tl);
  __nv_bfloat162 th = __halves2bfloat162(h0, h1);
  return *reinterpret_cast<unsigned*>(&th);
}

// ---------------------------------------------------------------------------
// fp32 -> (bf16 hi, bf16 lo) split conversion.
// ---------------------------------------------------------------------------
__global__ __launch_bounds__(256) void cvt_split_kernel(
    const float4* __restrict__ x, __nv_bfloat162* __restrict__ hi,
    __nv_bfloat162* __restrict__ lo, int n4) {
  int i = blockIdx.x * blockDim.x + threadIdx.x;
  if (i >= n4) return;
  float4 t = x[i];
  unsigned l0, l1;
  unsigned h0 = split2(t.x, t.y, l0);
  unsigned h1 = split2(t.z, t.w, l1);
  *(unsigned*)&hi[i * 2 + 0] = h0;
  *(unsigned*)&hi[i * 2 + 1] = h1;
  *(unsigned*)&lo[i * 2 + 0] = l0;
  *(unsigned*)&lo[i * 2 + 1] = l1;
}

// ---------------------------------------------------------------------------
// mma.sync GEMM: Y[M,N] = X[M,K] @ W[N,K]^T + bias, X/W as bf16 hi/lo.
// acc = Xhi*Whi + Xhi*Wlo + Xlo*Whi (3x m16n8k16, fp32 accum).
// 128x128 tile, k-chunk 32, double-buffered cp.async, 8 warps (64x32 each).
// 2 CTAs/SM (160KB smem, regs<=128) -> GEMM grid runs in a single wave.
// ---------------------------------------------------------------------------
#define GKP 40
#define SA_HI_B 0
#define SA_LO_B (128 * GKP * 2)
#define SB_HI_B (2 * 128 * GKP * 2)
#define SB_LO_B (3 * 128 * GKP * 2)
#define GBUF_B (4 * 128 * GKP * 2)
#define GEMM_SMEM_BYTES (2 * GBUF_B)  // 81920

template <bool SPLIT>
__global__ __launch_bounds__(256, 2) void gemm_mma_kernel(
    const __nv_bfloat16* __restrict__ Ahi, const __nv_bfloat16* __restrict__ Alo,
    const __nv_bfloat16* __restrict__ Bhi, const __nv_bfloat16* __restrict__ Blo,
    const float* __restrict__ bias, float* __restrict__ Y,
    __nv_bfloat16* __restrict__ Yhi, __nv_bfloat16* __restrict__ Ylo) {
  extern __shared__ __nv_bfloat16 sh[];
  const int tid = threadIdx.x;
  const int lane = tid & 31;
  const int warp = tid >> 5;
  const int wm = warp >> 2;
  const int wn = warp & 3;
  const int m0 = blockIdx.y * 128;
  const int n0 = blockIdx.x * 128;

  const int lrow = tid >> 1;
  const int lcol = (tid & 1) * 16;

  const unsigned sbase = (unsigned)__cvta_generic_to_shared(sh);
  const unsigned sdst = sbase + (unsigned)(lrow * GKP + lcol) * 2;

  const __nv_bfloat16* gAh = Ahi + (size_t)(m0 + lrow) * K_TOT + lcol;
  const __nv_bfloat16* gAl = Alo + (size_t)(m0 + lrow) * K_TOT + lcol;
  const __nv_bfloat16* gBh = Bhi + (size_t)(n0 + lrow) * K_TOT + lcol;
  const __nv_bfloat16* gBl = Blo + (size_t)(n0 + lrow) * K_TOT + lcol;

  float acc[4][4][4];
#pragma unroll
  for (int i = 0; i < 4; i++)
#pragma unroll
    for (int j = 0; j < 4; j++)
#pragma unroll
      for (int c = 0; c < 4; c++) acc[i][j][c] = 0.f;

  // A ldmatrix x4 per-lane offset (m16k16)
  const unsigned aoff = (unsigned)(((lane & 15) * GKP + ((lane >> 4) & 1) * 8) * 2);
  // B paired ldmatrix x4 offset (n16k16: lanes 0-15 rows 0-7 / 16-31 rows +8)
  const unsigned boff4 = (unsigned)((((lane & 7) + ((lane >> 4) & 1) * 8) * GKP +
                                     ((lane >> 3) & 1) * 8) * 2);

#define GEMM_ISSUE(k0, buf)                   \
  {                                           \
    unsigned d = sdst + (buf) * GBUF_B;       \
    cp16(d + SA_HI_B, gAh + (k0));            \
    cp16(d + SA_HI_B + 16, gAh + (k0) + 8);   \
    cp16(d + SA_LO_B, gAl + (k0));            \
    cp16(d + SA_LO_B + 16, gAl + (k0) + 8);   \
    cp16(d + SB_HI_B, gBh + (k0));            \
    cp16(d + SB_HI_B + 16, gBh + (k0) + 8);   \
    cp16(d + SB_LO_B, gBl + (k0));            \
    cp16(d + SB_LO_B + 16, gBl + (k0) + 8);   \
    asm volatile("cp.async.commit_group;\n"); \
  }

  GEMM_ISSUE(0, 0)

  const int NCHUNK = K_TOT / 32;
  int buf = 0;
  for (int t = 0; t < NCHUNK; t++) {
    if (t + 1 < NCHUNK) {
      GEMM_ISSUE((t + 1) * 32, buf ^ 1)
      asm volatile("cp.async.wait_group 1;\n");
    } else {
      asm volatile("cp.async.wait_group 0;\n");
    }
    __syncthreads();

    const unsigned base = sbase + buf * GBUF_B;
#pragma unroll
    for (int kk = 0; kk < 2; kk++) {
      const unsigned kadd = kk * 32;
      unsigned ah[4][4], al[4][4], bh[4][2], bl[4][2];
#pragma unroll
      for (int mt = 0; mt < 4; mt++) {
        unsigned rowb = (unsigned)((wm * 64 + mt * 16) * GKP * 2);
        ldm4(base + SA_HI_B + rowb + aoff + kadd, ah[mt]);
        ldm4(base + SA_LO_B + rowb + aoff + kadd, al[mt]);
      }
#pragma unroll
      for (int p = 0; p < 2; p++) {
        unsigned rowb = (unsigned)((wn * 32 + p * 16) * GKP * 2);
        unsigned tb[4];
        ldm4(base + SB_HI_B + rowb + boff4 + kadd, tb);
        bh[2 * p][0] = tb[0]; bh[2 * p][1] = tb[1];
        bh[2 * p + 1][0] = tb[2]; bh[2 * p + 1][1] = tb[3];
        ldm4(base + SB_LO_B + rowb + boff4 + kadd, tb);
        bl[2 * p][0] = tb[0]; bl[2 * p][1] = tb[1];
        bl[2 * p + 1][0] = tb[2]; bl[2 * p + 1][1] = tb[3];
      }
#pragma unroll
      for (int mt = 0; mt < 4; mt++)
#pragma unroll
        for (int nt = 0; nt < 4; nt++) mma16816(acc[mt][nt], ah[mt], bh[nt]);
#pragma unroll
      for (int mt = 0; mt < 4; mt++)
#pragma unroll
        for (int nt = 0; nt < 4; nt++) mma16816(acc[mt][nt], al[mt], bh[nt]);
#pragma unroll
      for (int mt = 0; mt < 4; mt++)
#pragma unroll
        for (int nt = 0; nt < 4; nt++) mma16816(acc[mt][nt], ah[mt], bl[nt]);
    }
    __syncthreads();
    buf ^= 1;
  }

#pragma unroll
  for (int mt = 0; mt < 4; mt++) {
    const int row = m0 + wm * 64 + mt * 16 + (lane >> 2);
#pragma unroll
    for (int nt = 0; nt < 4; nt++) {
      const int col = n0 + wn * 32 + nt * 8 + (lane & 3) * 2;
      float2 bv = *(const float2*)(bias + col);
      float v0 = acc[mt][nt][0] + bv.x;
      float v1 = acc[mt][nt][1] + bv.y;
      float v2 = acc[mt][nt][2] + bv.x;
      float v3 = acc[mt][nt][3] + bv.y;
      if (SPLIT) {
        unsigned lo0, lo1;
        unsigned hi0 = split2(v0, v1, lo0);
        unsigned hi1 = split2(v2, v3, lo1);
        *(unsigned*)&Yhi[(size_t)row * N_TOT + col] = hi0;
        *(unsigned*)&Ylo[(size_t)row * N_TOT + col] = lo0;
        *(unsigned*)&Yhi[(size_t)(row + 8) * N_TOT + col] = hi1;
        *(unsigned*)&Ylo[(size_t)(row + 8) * N_TOT + col] = lo1;
      } else {
        *(float2*)(Y + (size_t)row * N_TOT + col) = make_float2(v0, v1);
        *(float2*)(Y + (size_t)(row + 8) * N_TOT + col) = make_float2(v2, v3);
      }
    }
  }
}

// ---------------------------------------------------------------------------
// Tensor-core flash attention (bf16 hi/lo split, fp32 softmax).
// R4 change: K fragments via paired ldmatrix x4, V via paired ldmatrix x4.trans
// -> ldmatrix issue count halved vs R3.
// ---------------------------------------------------------------------------
#define ARL 72
#define AQH 0
#define AQL (128 * ARL)
#define AKV0 (2 * 128 * ARL)
#define KV_STRIDE (4 * 64 * ARL)
#define KH_OFF 0
#define KL_OFF (64 * ARL)
#define VH_OFF (2 * 64 * ARL)
#define VL_OFF (3 * 64 * ARL)
#define AMASK_H (AKV0 + 2 * KV_STRIDE)
#define ATTN_SMEM_BYTES (AMASK_H * 2 + 2 * 64 * 4)

__global__ __launch_bounds__(256, 1) void attn_mma_kernel(
    const __nv_bfloat16* __restrict__ qhi, const __nv_bfloat16* __restrict__ qlo,
    const __nv_bfloat16* __restrict__ khi, const __nv_bfloat16* __restrict__ klo,
    const __nv_bfloat16* __restrict__ vhi, const __nv_bfloat16* __restrict__ vlo,
    const unsigned* __restrict__ mask, const unsigned* __restrict__ semask,
    __nv_bfloat16* __restrict__ ohi, __nv_bfloat16* __restrict__ olo) {
  extern __shared__ __nv_bfloat16 sb[];
  float* mflag = (float*)(sb + AMASK_H);

  const int tid = threadIdx.x;
  const int lane = tid & 31;
  const int warp = tid >> 5;
  const int b = blockIdx.z;
  const int h = blockIdx.y;
  const int q0 = blockIdx.x * 128;
  const size_t qbase = ((size_t)(b * S_ + q0)) * D_ + h * DH_;
  const size_t kbase = ((size_t)(b * S_)) * D_ + h * DH_;
  const unsigned sbB = (unsigned)__cvta_generic_to_shared(sb);
  const unsigned* mk = mask + (size_t)b * S_;
  const unsigned* smk = semask + (size_t)b * S_;

#define ISSUE_KV(kt, st)                                                \
  {                                                                     \
    _Pragma("unroll") for (int r = 0; r < 2; r++) {                     \
      int idx = tid + 256 * r;                                          \
      int row = idx >> 3, ch = idx & 7;                                 \
      unsigned d = sbB +                                                \
          (unsigned)((AKV0 + (st)*KV_STRIDE + row * ARL + ch * 8) * 2); \
      size_t go = kbase + (size_t)((kt) + row) * D_ + ch * 8;           \
      cp16(d + KH_OFF * 2, khi + go);                                   \
      cp16(d + KL_OFF * 2, klo + go);                                   \
      cp16(d + VH_OFF * 2, vhi + go);                                   \
      cp16(d + VL_OFF * 2, vlo + go);                                   \
    }                                                                   \
  }

#pragma unroll
  for (int r = 0; r < 4; r++) {
    int idx = tid + 256 * r;
    int row = idx >> 3, ch = idx & 7;
    unsigned d = sbB + (unsigned)((row * ARL + ch * 8) * 2);
    size_t go = qbase + (size_t)row * D_ + ch * 8;
    cp16(d + AQH * 2, qhi + go);
    cp16(d + AQL * 2, qlo + go);
  }
  ISSUE_KV(0, 0)
  if (tid < 64) mflag[tid] = (mk[tid] | smk[tid]) ? 1.0f : 0.0f;
  asm volatile("cp.async.commit_group;\n");
  asm volatile("cp.async.wait_group 0;\n");
  __syncthreads();

  unsigned qh[4][4], ql[4][4];
  {
    const unsigned arow =
        (unsigned)(((warp * 16 + (lane & 15)) * ARL + ((lane >> 4) & 1) * 8) * 2);
#pragma unroll
    for (int kc = 0; kc < 4; kc++) {
      ldm4(sbB + AQH * 2 + arow + kc * 32, qh[kc]);
      ldm4(sbB + AQL * 2 + arow + kc * 32, ql[kc]);
    }
  }

  float m_i[2] = {-1e30f, -1e30f};
  float l_i[2] = {0.f, 0.f};
  float O[8][4];
#pragma unroll
  for (int nt = 0; nt < 8; nt++)
#pragma unroll
    for (int c = 0; c < 4; c++) O[nt][c] = 0.f;

  // paired K-load per-lane offset: rows (lane&7) + ((lane>>4)&1)*8,
  // k halves +((lane>>3)&1)*8
  const unsigned koff4 = (unsigned)((((lane & 7) + ((lane >> 4) & 1) * 8) * ARL +
                                     ((lane >> 3) & 1) * 8) * 2);

  int st = 0;
  for (int t = 0; t < S_ / 64; t++) {
    const int kt = t * 64;
    if (t + 1 < S_ / 64) {
      ISSUE_KV(kt + 64, st ^ 1)
      if (tid < 64)
        mflag[(st ^ 1) * 64 + tid] =
            (mk[kt + 64 + tid] | smk[kt + 64 + tid]) ? 1.0f : 0.0f;
      asm volatile("cp.async.commit_group;\n");
    }

    const unsigned kb = sbB + (unsigned)((AKV0 + st * KV_STRIDE) * 2);

    float S[8][4];
#pragma unroll
    for (int nt = 0; nt < 8; nt++)
#pragma unroll
      for (int c = 0; c < 4; c++) S[nt][c] = 0.f;

#pragma unroll
    for (int kc = 0; kc < 4; kc++) {
#pragma unroll
      for (int p = 0; p < 4; p++) {
        unsigned baddr = kb + (unsigned)((p * 16 * ARL + kc * 16) * 2) + koff4;
        unsigned tb[4], tl[4];
        ldm4(baddr + KH_OFF * 2, tb);
        ldm4(baddr + KL_OFF * 2, tl);
        mma16816(S[2 * p], qh[kc], tb);
        mma16816(S[2 * p], qh[kc], tl);
        mma16816(S[2 * p], ql[kc], tb);
        mma16816(S[2 * p + 1], qh[kc], tb + 2);
        mma16816(S[2 * p + 1], qh[kc], tl + 2);
        mma16816(S[2 * p + 1], ql[kc], tb + 2);
      }
    }

    const float* mf = mflag + st * 64;
    float rm0 = -1e30f, rm1 = -1e30f;
    float2 fl[8];
#pragma unroll
    for (int nt = 0; nt < 8; nt++) {
      fl[nt] = *(const float2*)&mf[nt * 8 + (lane & 3) * 2];
      float s0 = S[nt][0] * 0.125f;
      float s1 = S[nt][1] * 0.125f;
      float s2 = S[nt][2] * 0.125f;
      float s3 = S[nt][3] * 0.125f;
      s0 = (fl[nt].x != 0.f) ? -1e9f : s0;
      s1 = (fl[nt].y != 0.f) ? -1e9f : s1;
      s2 = (fl[nt].x != 0.f) ? -1e9f : s2;
      s3 = (fl[nt].y != 0.f) ? -1e9f : s3;
      S[nt][0] = s0; S[nt][1] = s1; S[nt][2] = s2; S[nt][3] = s3;
      rm0 = fmaxf(rm0, fmaxf(s0, s1));
      rm1 = fmaxf(rm1, fmaxf(s2, s3));
    }
    rm0 = fmaxf(rm0, __shfl_xor_sync(0xffffffffu, rm0, 1));
    rm0 = fmaxf(rm0, __shfl_xor_sync(0xffffffffu, rm0, 2));
    rm1 = fmaxf(rm1, __shfl_xor_sync(0xffffffffu, rm1, 1));
    rm1 = fmaxf(rm1, __shfl_xor_sync(0xffffffffu, rm1, 2));

    const float mn0 = fmaxf(m_i[0], rm0);
    const float mn1 = fmaxf(m_i[1], rm1);
    const float a0 = __expf(m_i[0] - mn0);
    const float a1 = __expf(m_i[1] - mn1);
    float rs0 = 0.f, rs1 = 0.f;
#pragma unroll
    for (int nt = 0; nt < 8; nt++) {
      S[nt][0] = __expf(S[nt][0] - mn0);
      S[nt][1] = __expf(S[nt][1] - mn0);
      S[nt][2] = __expf(S[nt][2] - mn1);
      S[nt][3] = __expf(S[nt][3] - mn1);
      rs0 += S[nt][0] + S[nt][1];
      rs1 += S[nt][2] + S[nt][3];
    }
    rs0 += __shfl_xor_sync(0xffffffffu, rs0, 1);
    rs0 += __shfl_xor_sync(0xffffffffu, rs0, 2);
    rs1 += __shfl_xor_sync(0xffffffffu, rs1, 1);
    rs1 += __shfl_xor_sync(0xffffffffu, rs1, 2);
    l_i[0] = l_i[0] * a0 + rs0;
    l_i[1] = l_i[1] * a1 + rs1;
    m_i[0] = mn0;
    m_i[1] = mn1;
#pragma unroll
    for (int nt = 0; nt < 8; nt++) {
      O[nt][0] *= a0;
      O[nt][1] *= a0;
      O[nt][2] *= a1;
      O[nt][3] *= a1;
    }

    // O += P V: V frags via paired ldm4t (two d8 tiles per load)
#pragma unroll
    for (int kc2 = 0; kc2 < 4; kc2++) {
      unsigned pa_h[4], pa_l[4];
      pa_h[0] = split2(S[2 * kc2][0], S[2 * kc2][1], pa_l[0]);
      pa_h[1] = split2(S[2 * kc2][2], S[2 * kc2][3], pa_l[1]);
      pa_h[2] = split2(S[2 * kc2 + 1][0], S[2 * kc2 + 1][1], pa_l[2]);
      pa_h[3] = split2(S[2 * kc2 + 1][2], S[2 * kc2 + 1][3], pa_l[3]);
#pragma unroll
      for (int p2 = 0; p2 < 4; p2++) {
        unsigned vaddr = kb +
            (unsigned)(((kc2 * 16 + (lane & 15)) * ARL + p2 * 16 +
                        ((lane >> 4) & 1) * 8) * 2);
        unsigned tv[4], tw[4];
        ldm4t(vaddr + VH_OFF * 2, tv);
        ldm4t(vaddr + VL_OFF * 2, tw);
        mma16816(O[2 * p2], pa_h, tv);
        mma16816(O[2 * p2], pa_h, tw);
        mma16816(O[2 * p2], pa_l, tv);
        mma16816(O[2 * p2 + 1], pa_h, tv + 2);
        mma16816(O[2 * p2 + 1], pa_h, tw + 2);
        mma16816(O[2 * p2 + 1], pa_l, tv + 2);
      }
    }

    if (t + 1 < S_ / 64) {
      asm volatile("cp.async.wait_group 0;\n");
      __syncthreads();
      st ^= 1;
    }
  }

  const float inv0 = 1.f / l_i[0];
  const float inv1 = 1.f / l_i[1];
  const int r0 = q0 + warp * 16 + (lane >> 2);
  const int colb = h * DH_ + (lane & 3) * 2;
#pragma unroll
  for (int nt = 0; nt < 8; nt++) {
    const int col = colb + nt * 8;
    unsigned lo0, lo1;
    unsigned hi0 = split2(O[nt][0] * inv0, O[nt][1] * inv0, lo0);
    unsigned hi1 = split2(O[nt][2] * inv1, O[nt][3] * inv1, lo1);
    *(unsigned*)&ohi[(size_t)(b * S_ + r0) * D_ + col] = hi0;
    *(unsigned*)&olo[(size_t)(b * S_ + r0) * D_ + col] = lo0;
    *(unsigned*)&ohi[(size_t)(b * S_ + r0 + 8) * D_ + col] = hi1;
    *(unsigned*)&olo[(size_t)(b * S_ + r0 + 8) * D_ + col] = lo1;
  }
}

// ---------------------------------------------------------------------------
// Launch
// ---------------------------------------------------------------------------
extern "C" void kernel_launch(void* const* d_in, const int* in_sizes, int n_in,
                              void* d_out, int out_size) {
  const float* v = (const float*)d_in[0];
  const float* k = (const float*)d_in[1];
  const float* q = (const float*)d_in[2];
  const unsigned* mask = (const unsigned*)d_in[3];
  const unsigned* semask = (const unsigned*)d_in[4];
  const float* Wv = (const float*)d_in[5];
  const float* bv = (const float*)d_in[6];
  const float* Wk = (const float*)d_in[7];
  const float* bk = (const float*)d_in[8];
  const float* Wq = (const float*)d_in[9];
  const float* bq = (const float*)d_in[10];
  const float* Wm = (const float*)d_in[11];
  const float* bm = (const float*)d_in[12];
  float* out = (float*)d_out;

  __nv_bfloat16 *xhi, *xlo, *whi, *wlo;
  __nv_bfloat16 *qh, *ql, *kh, *kl, *vh, *vl, *ah, *al;
  cudaGetSymbolAddress((void**)&xhi, g_xhi);
  cudaGetSymbolAddress((void**)&xlo, g_xlo);
  cudaGetSymbolAddress((void**)&whi, g_whi);
  cudaGetSymbolAddress((void**)&wlo, g_wlo);
  cudaGetSymbolAddress((void**)&qh, g_qh);
  cudaGetSymbolAddress((void**)&ql, g_ql);
  cudaGetSymbolAddress((void**)&kh, g_kh);
  cudaGetSymbolAddress((void**)&kl, g_kl);
  cudaGetSymbolAddress((void**)&vh, g_vh);
  cudaGetSymbolAddress((void**)&vl, g_vl);
  cudaGetSymbolAddress((void**)&ah, g_ah);
  cudaGetSymbolAddress((void**)&al, g_al);

  cudaFuncSetAttribute(attn_mma_kernel,
                       cudaFuncAttributeMaxDynamicSharedMemorySize,
                       ATTN_SMEM_BYTES);
  cudaFuncSetAttribute(gemm_mma_kernel<true>,
                       cudaFuncAttributeMaxDynamicSharedMemorySize,
                       GEMM_SMEM_BYTES);
  cudaFuncSetAttribute(gemm_mma_kernel<false>,
                       cudaFuncAttributeMaxDynamicSharedMemorySize,
                       GEMM_SMEM_BYTES);

  const int nx4 = M_TOT * K_TOT / 4;
  const int nw4 = N_TOT * K_TOT / 4;
  const dim3 cblk(256);
  const dim3 cgx((nx4 + 255) / 256);
  const dim3 cgw((nw4 + 255) / 256);
  const dim3 ggrid(N_TOT / 128, M_TOT / 128);  // (8, 32)
  const dim3 gblk(256);

#define RUN_PROJ(XPTR, WPTR, BPTR, YH, YL)                                     \
  cvt_split_kernel<<<cgx, cblk>>>((const float4*)(XPTR), (__nv_bfloat162*)xhi, \
                                  (__nv_bfloat162*)xlo, nx4);                  \
  cvt_split_kernel<<<cgw, cblk>>>((const float4*)(WPTR), (__nv_bfloat162*)whi, \
                                  (__nv_bfloat162*)wlo, nw4);                  \
  gemm_mma_kernel<true><<<ggrid, gblk, GEMM_SMEM_BYTES>>>(                     \
      xhi, xlo, whi, wlo, (BPTR), nullptr, (YH), (YL));

  RUN_PROJ(v, Wv, bv, vh, vl)
  RUN_PROJ(k, Wk, bk, kh, kl)
  RUN_PROJ(q, Wq, bq, qh, ql)

  attn_mma_kernel<<<dim3(S_ / 128, H_, B_), dim3(256), ATTN_SMEM_BYTES>>>(
      qh, ql, kh, kl, vh, vl, mask, semask, ah, al);

  cvt_split_kernel<<<cgw, cblk>>>((const float4*)Wm, (__nv_bfloat162*)whi,
                                  (__nv_bfloat162*)wlo, nw4);
  gemm_mma_kernel<false><<<ggrid, gblk, GEMM_SMEM_BYTES>>>(
      ah, al, whi, wlo, bm, out, nullptr, nullptr);
}

// round 6
// speedup vs baseline: 2.4942x; 1.0734x over previous
#include <cuda_runtime.h>
#include <cuda_bf16.h>
#include <cstdint>

// Problem constants
#define B_ 4
#define S_ 1024
#define D_ 1024
#define H_ 16
#define DH_ 64
#define M_TOT (B_ * S_)   // 4096
#define N_TOT D_          // 1024
#define K_TOT D_          // 1024

// Scratch (allocation-free rule: __device__ globals)
// input staging (v,k,q) hi/lo
__device__ __nv_bfloat16 g_ixh[3 * M_TOT * K_TOT];
__device__ __nv_bfloat16 g_ixl[3 * M_TOT * K_TOT];
// weights (Wv,Wk,Wq,Wm) hi/lo
__device__ __nv_bfloat16 g_wh[4 * N_TOT * K_TOT];
__device__ __nv_bfloat16 g_wl[4 * N_TOT * K_TOT];
// projection outputs
__device__ __nv_bfloat16 g_qh[M_TOT * D_];
__device__ __nv_bfloat16 g_ql[M_TOT * D_];
__device__ __nv_bfloat16 g_kh[M_TOT * D_];
__device__ __nv_bfloat16 g_kl[M_TOT * D_];
__device__ __nv_bfloat16 g_vh[M_TOT * D_];
__device__ __nv_bfloat16 g_vl[M_TOT * D_];
// attention output
__device__ __nv_bfloat16 g_ah[M_TOT * D_];
__device__ __nv_bfloat16 g_al[M_TOT * D_];

// ---------------------------------------------------------------------------
// helpers
// ---------------------------------------------------------------------------
__device__ __forceinline__ void cp16(unsigned dst, const void* src) {
  asm volatile("cp.async.cg.shared.global [%0], [%1], 16;\n" ::"r"(dst),
               "l"(src));
}
__device__ __forceinline__ void ldm4(unsigned addr, unsigned* r) {
  asm volatile("ldmatrix.sync.aligned.m8n8.x4.shared.b16 {%0,%1,%2,%3}, [%4];"
               : "=r"(r[0]), "=r"(r[1]), "=r"(r[2]), "=r"(r[3])
               : "r"(addr));
}
__device__ __forceinline__ void ldm4t(unsigned addr, unsigned* r) {
  asm volatile(
      "ldmatrix.sync.aligned.m8n8.x4.trans.shared.b16 {%0,%1,%2,%3}, [%4];"
      : "=r"(r[0]), "=r"(r[1]), "=r"(r[2]), "=r"(r[3])
      : "r"(addr));
}
__device__ __forceinline__ void mma16816(float* c, const unsigned* a,
                                         const unsigned* b) {
  asm volatile(
      "mma.sync.aligned.m16n8k16.row.col.f32.bf16.bf16.f32 "
      "{%0,%1,%2,%3},{%4,%5,%6,%7},{%8,%9},{%0,%1,%2,%3};"
      : "+f"(c[0]), "+f"(c[1]), "+f"(c[2]), "+f"(c[3])
      : "r"(a[0]), "r"(a[1]), "r"(a[2]), "r"(a[3]), "r"(b[0]), "r"(b[1]));
}
__device__ __forceinline__ unsigned split2(float x0, float x1, unsigned& lo) {
  __nv_bfloat16 h0 = __float2bfloat16(x0);
  __nv_bfloat16 h1 = __float2bfloat16(x1);
  __nv_bfloat16 l0 = __float2bfloat16(x0 - __bfloat162float(h0));
  __nv_bfloat16 l1 = __float2bfloat16(x1 - __bfloat162float(h1));
  __nv_bfloat162 tl = __halves2bfloat162(l0, l1);
  lo = *reinterpret_cast<unsigned*>(&tl);
  __nv_bfloat162 th = __halves2bfloat162(h0, h1);
  return *reinterpret_cast<unsigned*>(&th);
}

// ---------------------------------------------------------------------------
// fused fp32 -> (bf16 hi, lo) conversions.  2x float4 per thread, uint4 out.
// ---------------------------------------------------------------------------
__device__ __forceinline__ void cvt_body(const float4* __restrict__ x,
                                         uint4* __restrict__ hi,
                                         uint4* __restrict__ lo, int i) {
  float4 a = x[2 * i];
  float4 b = x[2 * i + 1];
  unsigned l0, l1, l2, l3;
  unsigned h0 = split2(a.x, a.y, l0);
  unsigned h1 = split2(a.z, a.w, l1);
  unsigned h2 = split2(b.x, b.y, l2);
  unsigned h3 = split2(b.z, b.w, l3);
  hi[i] = make_uint4(h0, h1, h2, h3);
  lo[i] = make_uint4(l0, l1, l2, l3);
}

__global__ __launch_bounds__(256) void cvt_in_kernel(
    const float* __restrict__ v, const float* __restrict__ k,
    const float* __restrict__ q, __nv_bfloat16* __restrict__ hi,
    __nv_bfloat16* __restrict__ lo) {
  const int z = blockIdx.z;
  const float* src = (z == 0) ? v : (z == 1) ? k : q;
  const int i = blockIdx.x * 256 + threadIdx.x;  // 8 floats per thread
  cvt_body((const float4*)src, (uint4*)(hi + (size_t)z * M_TOT * K_TOT),
           (uint4*)(lo + (size_t)z * M_TOT * K_TOT), i);
}

__global__ __launch_bounds__(256) void cvt_w_kernel(
    const float* __restrict__ w0, const float* __restrict__ w1,
    const float* __restrict__ w2, const float* __restrict__ w3,
    __nv_bfloat16* __restrict__ hi, __nv_bfloat16* __restrict__ lo) {
  const int z = blockIdx.z;
  const float* src = (z == 0) ? w0 : (z == 1) ? w1 : (z == 2) ? w2 : w3;
  const int i = blockIdx.x * 256 + threadIdx.x;
  cvt_body((const float4*)src, (uint4*)(hi + (size_t)z * N_TOT * K_TOT),
           (uint4*)(lo + (size_t)z * N_TOT * K_TOT), i);
}

// ---------------------------------------------------------------------------
// mma.sync GEMM body: Y[M,N] = X[M,K] @ W[N,K]^T + bias, X/W as bf16 hi/lo.
// acc = Xhi*Whi + Xhi*Wlo + Xlo*Whi.  128x128 tile, k-chunk 32, 2 CTAs/SM.
// ---------------------------------------------------------------------------
#define GKP 40
#define SA_HI_B 0
#define SA_LO_B (128 * GKP * 2)
#define SB_HI_B (2 * 128 * GKP * 2)
#define SB_LO_B (3 * 128 * GKP * 2)
#define GBUF_B (4 * 128 * GKP * 2)
#define GEMM_SMEM_BYTES (2 * GBUF_B)  // 81920

template <bool SPLIT>
__device__ __forceinline__ void gemm_body(
    const __nv_bfloat16* __restrict__ Ahi, const __nv_bfloat16* __restrict__ Alo,
    const __nv_bfloat16* __restrict__ Bhi, const __nv_bfloat16* __restrict__ Blo,
    const float* __restrict__ bias, float* __restrict__ Y,
    __nv_bfloat16* __restrict__ Yhi, __nv_bfloat16* __restrict__ Ylo,
    __nv_bfloat16* sh) {
  const int tid = threadIdx.x;
  const int lane = tid & 31;
  const int warp = tid >> 5;
  const int wm = warp >> 2;
  const int wn = warp & 3;
  const int m0 = blockIdx.y * 128;
  const int n0 = blockIdx.x * 128;

  const int lrow = tid >> 1;
  const int lcol = (tid & 1) * 16;

  const unsigned sbase = (unsigned)__cvta_generic_to_shared(sh);
  const unsigned sdst = sbase + (unsigned)(lrow * GKP + lcol) * 2;

  const __nv_bfloat16* gAh = Ahi + (size_t)(m0 + lrow) * K_TOT + lcol;
  const __nv_bfloat16* gAl = Alo + (size_t)(m0 + lrow) * K_TOT + lcol;
  const __nv_bfloat16* gBh = Bhi + (size_t)(n0 + lrow) * K_TOT + lcol;
  const __nv_bfloat16* gBl = Blo + (size_t)(n0 + lrow) * K_TOT + lcol;

  float acc[4][4][4];
#pragma unroll
  for (int i = 0; i < 4; i++)
#pragma unroll
    for (int j = 0; j < 4; j++)
#pragma unroll
      for (int c = 0; c < 4; c++) acc[i][j][c] = 0.f;

  const unsigned aoff = (unsigned)(((lane & 15) * GKP + ((lane >> 4) & 1) * 8) * 2);
  const unsigned boff4 = (unsigned)((((lane & 7) + ((lane >> 4) & 1) * 8) * GKP +
                                     ((lane >> 3) & 1) * 8) * 2);

#define GEMM_ISSUE(k0, buf)                   \
  {                                           \
    unsigned d = sdst + (buf) * GBUF_B;       \
    cp16(d + SA_HI_B, gAh + (k0));            \
    cp16(d + SA_HI_B + 16, gAh + (k0) + 8);   \
    cp16(d + SA_LO_B, gAl + (k0));            \
    cp16(d + SA_LO_B + 16, gAl + (k0) + 8);   \
    cp16(d + SB_HI_B, gBh + (k0));            \
    cp16(d + SB_HI_B + 16, gBh + (k0) + 8);   \
    cp16(d + SB_LO_B, gBl + (k0));            \
    cp16(d + SB_LO_B + 16, gBl + (k0) + 8);   \
    asm volatile("cp.async.commit_group;\n"); \
  }

  GEMM_ISSUE(0, 0)

  const int NCHUNK = K_TOT / 32;
  int buf = 0;
  for (int t = 0; t < NCHUNK; t++) {
    if (t + 1 < NCHUNK) {
      GEMM_ISSUE((t + 1) * 32, buf ^ 1)
      asm volatile("cp.async.wait_group 1;\n");
    } else {
      asm volatile("cp.async.wait_group 0;\n");
    }
    __syncthreads();

    const unsigned base = sbase + buf * GBUF_B;
#pragma unroll
    for (int kk = 0; kk < 2; kk++) {
      const unsigned kadd = kk * 32;
      unsigned ah[4][4], al[4][4], bh[4][2], bl[4][2];
#pragma unroll
      for (int mt = 0; mt < 4; mt++) {
        unsigned rowb = (unsigned)((wm * 64 + mt * 16) * GKP * 2);
        ldm4(base + SA_HI_B + rowb + aoff + kadd, ah[mt]);
        ldm4(base + SA_LO_B + rowb + aoff + kadd, al[mt]);
      }
#pragma unroll
      for (int p = 0; p < 2; p++) {
        unsigned rowb = (unsigned)((wn * 32 + p * 16) * GKP * 2);
        unsigned tb[4];
        ldm4(base + SB_HI_B + rowb + boff4 + kadd, tb);
        bh[2 * p][0] = tb[0]; bh[2 * p][1] = tb[1];
        bh[2 * p + 1][0] = tb[2]; bh[2 * p + 1][1] = tb[3];
        ldm4(base + SB_LO_B + rowb + boff4 + kadd, tb);
        bl[2 * p][0] = tb[0]; bl[2 * p][1] = tb[1];
        bl[2 * p + 1][0] = tb[2]; bl[2 * p + 1][1] = tb[3];
      }
#pragma unroll
      for (int mt = 0; mt < 4; mt++)
#pragma unroll
        for (int nt = 0; nt < 4; nt++) mma16816(acc[mt][nt], ah[mt], bh[nt]);
#pragma unroll
      for (int mt = 0; mt < 4; mt++)
#pragma unroll
        for (int nt = 0; nt < 4; nt++) mma16816(acc[mt][nt], al[mt], bh[nt]);
#pragma unroll
      for (int mt = 0; mt < 4; mt++)
#pragma unroll
        for (int nt = 0; nt < 4; nt++) mma16816(acc[mt][nt], ah[mt], bl[nt]);
    }
    __syncthreads();
    buf ^= 1;
  }

#pragma unroll
  for (int mt = 0; mt < 4; mt++) {
    const int row = m0 + wm * 64 + mt * 16 + (lane >> 2);
#pragma unroll
    for (int nt = 0; nt < 4; nt++) {
      const int col = n0 + wn * 32 + nt * 8 + (lane & 3) * 2;
      float2 bv = *(const float2*)(bias + col);
      float v0 = acc[mt][nt][0] + bv.x;
      float v1 = acc[mt][nt][1] + bv.y;
      float v2 = acc[mt][nt][2] + bv.x;
      float v3 = acc[mt][nt][3] + bv.y;
      if (SPLIT) {
        unsigned lo0, lo1;
        unsigned hi0 = split2(v0, v1, lo0);
        unsigned hi1 = split2(v2, v3, lo1);
        *(unsigned*)&Yhi[(size_t)row * N_TOT + col] = hi0;
        *(unsigned*)&Ylo[(size_t)row * N_TOT + col] = lo0;
        *(unsigned*)&Yhi[(size_t)(row + 8) * N_TOT + col] = hi1;
        *(unsigned*)&Ylo[(size_t)(row + 8) * N_TOT + col] = lo1;
      } else {
        *(float2*)(Y + (size_t)row * N_TOT + col) = make_float2(v0, v1);
        *(float2*)(Y + (size_t)(row + 8) * N_TOT + col) = make_float2(v2, v3);
      }
    }
  }
}

// Batched projection GEMM: grid.z selects (input, weight, bias, output).
struct ProjArgs {
  const __nv_bfloat16* Ah[3];
  const __nv_bfloat16* Al[3];
  const __nv_bfloat16* Bh[3];
  const __nv_bfloat16* Bl[3];
  const float* bias[3];
  __nv_bfloat16* Yh[3];
  __nv_bfloat16* Yl[3];
};

__global__ __launch_bounds__(256, 2) void gemm_proj_kernel(ProjArgs a) {
  extern __shared__ __nv_bfloat16 sh[];
  const int z = blockIdx.z;
  gemm_body<true>(a.Ah[z], a.Al[z], a.Bh[z], a.Bl[z], a.bias[z], nullptr,
                  a.Yh[z], a.Yl[z], sh);
}

__global__ __launch_bounds__(256, 2) void gemm_out_kernel(
    const __nv_bfloat16* __restrict__ Ahi, const __nv_bfloat16* __restrict__ Alo,
    const __nv_bfloat16* __restrict__ Bhi, const __nv_bfloat16* __restrict__ Blo,
    const float* __restrict__ bias, float* __restrict__ Y) {
  extern __shared__ __nv_bfloat16 sh[];
  gemm_body<false>(Ahi, Alo, Bhi, Blo, bias, Y, nullptr, nullptr, sh);
}

// ---------------------------------------------------------------------------
// Tensor-core flash attention (bf16 hi/lo split, fp32 softmax).
// R5 change: __launch_bounds__(256, 2) -> 2 CTAs/SM (smem 111KB*2 fits 228KB).
// ---------------------------------------------------------------------------
#define ARL 72
#define AQH 0
#define AQL (128 * ARL)
#define AKV0 (2 * 128 * ARL)
#define KV_STRIDE (4 * 64 * ARL)
#define KH_OFF 0
#define KL_OFF (64 * ARL)
#define VH_OFF (2 * 64 * ARL)
#define VL_OFF (3 * 64 * ARL)
#define AMASK_H (AKV0 + 2 * KV_STRIDE)
#define ATTN_SMEM_BYTES (AMASK_H * 2 + 2 * 64 * 4)

__global__ __launch_bounds__(256, 2) void attn_mma_kernel(
    const __nv_bfloat16* __restrict__ qhi, const __nv_bfloat16* __restrict__ qlo,
    const __nv_bfloat16* __restrict__ khi, const __nv_bfloat16* __restrict__ klo,
    const __nv_bfloat16* __restrict__ vhi, const __nv_bfloat16* __restrict__ vlo,
    const unsigned* __restrict__ mask, const unsigned* __restrict__ semask,
    __nv_bfloat16* __restrict__ ohi, __nv_bfloat16* __restrict__ olo) {
  extern __shared__ __nv_bfloat16 sb[];
  float* mflag = (float*)(sb + AMASK_H);

  const int tid = threadIdx.x;
  const int lane = tid & 31;
  const int warp = tid >> 5;
  const int b = blockIdx.z;
  const int h = blockIdx.y;
  const int q0 = blockIdx.x * 128;
  const size_t qbase = ((size_t)(b * S_ + q0)) * D_ + h * DH_;
  const size_t kbase = ((size_t)(b * S_)) * D_ + h * DH_;
  const unsigned sbB = (unsigned)__cvta_generic_to_shared(sb);
  const unsigned* mk = mask + (size_t)b * S_;
  const unsigned* smk = semask + (size_t)b * S_;

#define ISSUE_KV(kt, st)                                                \
  {                                                                     \
    _Pragma("unroll") for (int r = 0; r < 2; r++) {                     \
      int idx = tid + 256 * r;                                          \
      int row = idx >> 3, ch = idx & 7;                                 \
      unsigned d = sbB +                                                \
          (unsigned)((AKV0 + (st)*KV_STRIDE + row * ARL + ch * 8) * 2); \
      size_t go = kbase + (size_t)((kt) + row) * D_ + ch * 8;           \
      cp16(d + KH_OFF * 2, khi + go);                                   \
      cp16(d + KL_OFF * 2, klo + go);                                   \
      cp16(d + VH_OFF * 2, vhi + go);                                   \
      cp16(d + VL_OFF * 2, vlo + go);                                   \
    }                                                                   \
  }

#pragma unroll
  for (int r = 0; r < 4; r++) {
    int idx = tid + 256 * r;
    int row = idx >> 3, ch = idx & 7;
    unsigned d = sbB + (unsigned)((row * ARL + ch * 8) * 2);
    size_t go = qbase + (size_t)row * D_ + ch * 8;
    cp16(d + AQH * 2, qhi + go);
    cp16(d + AQL * 2, qlo + go);
  }
  ISSUE_KV(0, 0)
  if (tid < 64) mflag[tid] = (mk[tid] | smk[tid]) ? 1.0f : 0.0f;
  asm volatile("cp.async.commit_group;\n");
  asm volatile("cp.async.wait_group 0;\n");
  __syncthreads();

  unsigned qh[4][4], ql[4][4];
  {
    const unsigned arow =
        (unsigned)(((warp * 16 + (lane & 15)) * ARL + ((lane >> 4) & 1) * 8) * 2);
#pragma unroll
    for (int kc = 0; kc < 4; kc++) {
      ldm4(sbB + AQH * 2 + arow + kc * 32, qh[kc]);
      ldm4(sbB + AQL * 2 + arow + kc * 32, ql[kc]);
    }
  }

  float m_i[2] = {-1e30f, -1e30f};
  float l_i[2] = {0.f, 0.f};
  float O[8][4];
#pragma unroll
  for (int nt = 0; nt < 8; nt++)
#pragma unroll
    for (int c = 0; c < 4; c++) O[nt][c] = 0.f;

  const unsigned koff4 = (unsigned)((((lane & 7) + ((lane >> 4) & 1) * 8) * ARL +
                                     ((lane >> 3) & 1) * 8) * 2);

  int st = 0;
  for (int t = 0; t < S_ / 64; t++) {
    const int kt = t * 64;
    if (t + 1 < S_ / 64) {
      ISSUE_KV(kt + 64, st ^ 1)
      if (tid < 64)
        mflag[(st ^ 1) * 64 + tid] =
            (mk[kt + 64 + tid] | smk[kt + 64 + tid]) ? 1.0f : 0.0f;
      asm volatile("cp.async.commit_group;\n");
    }

    const unsigned kb = sbB + (unsigned)((AKV0 + st * KV_STRIDE) * 2);

    float S[8][4];
#pragma unroll
    for (int nt = 0; nt < 8; nt++)
#pragma unroll
      for (int c = 0; c < 4; c++) S[nt][c] = 0.f;

#pragma unroll
    for (int kc = 0; kc < 4; kc++) {
#pragma unroll
      for (int p = 0; p < 4; p++) {
        unsigned baddr = kb + (unsigned)((p * 16 * ARL + kc * 16) * 2) + koff4;
        unsigned tb[4], tl[4];
        ldm4(baddr + KH_OFF * 2, tb);
        ldm4(baddr + KL_OFF * 2, tl);
        mma16816(S[2 * p], qh[kc], tb);
        mma16816(S[2 * p], qh[kc], tl);
        mma16816(S[2 * p], ql[kc], tb);
        mma16816(S[2 * p + 1], qh[kc], tb + 2);
        mma16816(S[2 * p + 1], qh[kc], tl + 2);
        mma16816(S[2 * p + 1], ql[kc], tb + 2);
      }
    }

    const float* mf = mflag + st * 64;
    float rm0 = -1e30f, rm1 = -1e30f;
    float2 fl[8];
#pragma unroll
    for (int nt = 0; nt < 8; nt++) {
      fl[nt] = *(const float2*)&mf[nt * 8 + (lane & 3) * 2];
      float s0 = S[nt][0] * 0.125f;
      float s1 = S[nt][1] * 0.125f;
      float s2 = S[nt][2] * 0.125f;
      float s3 = S[nt][3] * 0.125f;
      s0 = (fl[nt].x != 0.f) ? -1e9f : s0;
      s1 = (fl[nt].y != 0.f) ? -1e9f : s1;
      s2 = (fl[nt].x != 0.f) ? -1e9f : s2;
      s3 = (fl[nt].y != 0.f) ? -1e9f : s3;
      S[nt][0] = s0; S[nt][1] = s1; S[nt][2] = s2; S[nt][3] = s3;
      rm0 = fmaxf(rm0, fmaxf(s0, s1));
      rm1 = fmaxf(rm1, fmaxf(s2, s3));
    }
    rm0 = fmaxf(rm0, __shfl_xor_sync(0xffffffffu, rm0, 1));
    rm0 = fmaxf(rm0, __shfl_xor_sync(0xffffffffu, rm0, 2));
    rm1 = fmaxf(rm1, __shfl_xor_sync(0xffffffffu, rm1, 1));
    rm1 = fmaxf(rm1, __shfl_xor_sync(0xffffffffu, rm1, 2));

    const float mn0 = fmaxf(m_i[0], rm0);
    const float mn1 = fmaxf(m_i[1], rm1);
    const float a0 = __expf(m_i[0] - mn0);
    const float a1 = __expf(m_i[1] - mn1);
    float rs0 = 0.f, rs1 = 0.f;
#pragma unroll
    for (int nt = 0; nt < 8; nt++) {
      S[nt][0] = __expf(S[nt][0] - mn0);
      S[nt][1] = __expf(S[nt][1] - mn0);
      S[nt][2] = __expf(S[nt][2] - mn1);
      S[nt][3] = __expf(S[nt][3] - mn1);
      rs0 += S[nt][0] + S[nt][1];
      rs1 += S[nt][2] + S[nt][3];
    }
    rs0 += __shfl_xor_sync(0xffffffffu, rs0, 1);
    rs0 += __shfl_xor_sync(0xffffffffu, rs0, 2);
    rs1 += __shfl_xor_sync(0xffffffffu, rs1, 1);
    rs1 += __shfl_xor_sync(0xffffffffu, rs1, 2);
    l_i[0] = l_i[0] * a0 + rs0;
    l_i[1] = l_i[1] * a1 + rs1;
    m_i[0] = mn0;
    m_i[1] = mn1;
#pragma unroll
    for (int nt = 0; nt < 8; nt++) {
      O[nt][0] *= a0;
      O[nt][1] *= a0;
      O[nt][2] *= a1;
      O[nt][3] *= a1;
    }

#pragma unroll
    for (int kc2 = 0; kc2 < 4; kc2++) {
      unsigned pa_h[4], pa_l[4];
      pa_h[0] = split2(S[2 * kc2][0], S[2 * kc2][1], pa_l[0]);
      pa_h[1] = split2(S[2 * kc2][2], S[2 * kc2][3], pa_l[1]);
      pa_h[2] = split2(S[2 * kc2 + 1][0], S[2 * kc2 + 1][1], pa_l[2]);
      pa_h[3] = split2(S[2 * kc2 + 1][2], S[2 * kc2 + 1][3], pa_l[3]);
#pragma unroll
      for (int p2 = 0; p2 < 4; p2++) {
        unsigned vaddr = kb +
            (unsigned)(((kc2 * 16 + (lane & 15)) * ARL + p2 * 16 +
                        ((lane >> 4) & 1) * 8) * 2);
        unsigned tv[4], tw[4];
        ldm4t(vaddr + VH_OFF * 2, tv);
        ldm4t(vaddr + VL_OFF * 2, tw);
        mma16816(O[2 * p2], pa_h, tv);
        mma16816(O[2 * p2], pa_h, tw);
        mma16816(O[2 * p2], pa_l, tv);
        mma16816(O[2 * p2 + 1], pa_h, tv + 2);
        mma16816(O[2 * p2 + 1], pa_h, tw + 2);
        mma16816(O[2 * p2 + 1], pa_l, tv + 2);
      }
    }

    if (t + 1 < S_ / 64) {
      asm volatile("cp.async.wait_group 0;\n");
      __syncthreads();
      st ^= 1;
    }
  }

  const float inv0 = 1.f / l_i[0];
  const float inv1 = 1.f / l_i[1];
  const int r0 = q0 + warp * 16 + (lane >> 2);
  const int colb = h * DH_ + (lane & 3) * 2;
#pragma unroll
  for (int nt = 0; nt < 8; nt++) {
    const int col = colb + nt * 8;
    unsigned lo0, lo1;
    unsigned hi0 = split2(O[nt][0] * inv0, O[nt][1] * inv0, lo0);
    unsigned hi1 = split2(O[nt][2] * inv1, O[nt][3] * inv1, lo1);
    *(unsigned*)&ohi[(size_t)(b * S_ + r0) * D_ + col] = hi0;
    *(unsigned*)&olo[(size_t)(b * S_ + r0) * D_ + col] = lo0;
    *(unsigned*)&ohi[(size_t)(b * S_ + r0 + 8) * D_ + col] = hi1;
    *(unsigned*)&olo[(size_t)(b * S_ + r0 + 8) * D_ + col] = lo1;
  }
}

// ---------------------------------------------------------------------------
// Launch:  cvt_in | cvt_w | proj_gemm(z=3) | attn | out_gemm   (5 launches;
// attn sits at user launch index 3 == the slot ncu captures)
// ---------------------------------------------------------------------------
extern "C" void kernel_launch(void* const* d_in, const int* in_sizes, int n_in,
                              void* d_out, int out_size) {
  const float* v = (const float*)d_in[0];
  const float* k = (const float*)d_in[1];
  const float* q = (const float*)d_in[2];
  const unsigned* mask = (const unsigned*)d_in[3];
  const unsigned* semask = (const unsigned*)d_in[4];
  const float* Wv = (const float*)d_in[5];
  const float* bv = (const float*)d_in[6];
  const float* Wk = (const float*)d_in[7];
  const float* bk = (const float*)d_in[8];
  const float* Wq = (const float*)d_in[9];
  const float* bq = (const float*)d_in[10];
  const float* Wm = (const float*)d_in[11];
  const float* bm = (const float*)d_in[12];
  float* out = (float*)d_out;

  __nv_bfloat16 *ixh, *ixl, *wh, *wl;
  __nv_bfloat16 *qh, *ql, *kh, *kl, *vh, *vl, *ah, *al;
  cudaGetSymbolAddress((void**)&ixh, g_ixh);
  cudaGetSymbolAddress((void**)&ixl, g_ixl);
  cudaGetSymbolAddress((void**)&wh, g_wh);
  cudaGetSymbolAddress((void**)&wl, g_wl);
  cudaGetSymbolAddress((void**)&qh, g_qh);
  cudaGetSymbolAddress((void**)&ql, g_ql);
  cudaGetSymbolAddress((void**)&kh, g_kh);
  cudaGetSymbolAddress((void**)&kl, g_kl);
  cudaGetSymbolAddress((void**)&vh, g_vh);
  cudaGetSymbolAddress((void**)&vl, g_vl);
  cudaGetSymbolAddress((void**)&ah, g_ah);
  cudaGetSymbolAddress((void**)&al, g_al);

  cudaFuncSetAttribute(attn_mma_kernel,
                       cudaFuncAttributeMaxDynamicSharedMemorySize,
                       ATTN_SMEM_BYTES);
  cudaFuncSetAttribute(gemm_proj_kernel,
                       cudaFuncAttributeMaxDynamicSharedMemorySize,
                       GEMM_SMEM_BYTES);
  cudaFuncSetAttribute(gemm_out_kernel,
                       cudaFuncAttributeMaxDynamicSharedMemorySize,
                       GEMM_SMEM_BYTES);

  const size_t NK = (size_t)N_TOT * K_TOT;
  const size_t MK = (size_t)M_TOT * K_TOT;

  // 1. convert inputs (v,k,q): 8 floats/thread
  cvt_in_kernel<<<dim3(MK / 8 / 256, 1, 3), 256>>>(v, k, q, ixh, ixl);
  // 2. convert weights (Wv,Wk,Wq,Wm)
  cvt_w_kernel<<<dim3(NK / 8 / 256, 1, 4), 256>>>(Wv, Wk, Wq, Wm, wh, wl);

  // 3. batched projections: z=0 V, z=1 K, z=2 Q
  ProjArgs pa;
  pa.Ah[0] = ixh;          pa.Al[0] = ixl;
  pa.Ah[1] = ixh + MK;     pa.Al[1] = ixl + MK;
  pa.Ah[2] = ixh + 2 * MK; pa.Al[2] = ixl + 2 * MK;
  pa.Bh[0] = wh;           pa.Bl[0] = wl;
  pa.Bh[1] = wh + NK;      pa.Bl[1] = wl + NK;
  pa.Bh[2] = wh + 2 * NK;  pa.Bl[2] = wl + 2 * NK;
  pa.bias[0] = bv; pa.bias[1] = bk; pa.bias[2] = bq;
  pa.Yh[0] = vh; pa.Yl[0] = vl;
  pa.Yh[1] = kh; pa.Yl[1] = kl;
  pa.Yh[2] = qh; pa.Yl[2] = ql;
  gemm_proj_kernel<<<dim3(N_TOT / 128, M_TOT / 128, 3), 256,
                     GEMM_SMEM_BYTES>>>(pa);

  // 4. attention (profiled slot)
  attn_mma_kernel<<<dim3(S_ / 128, H_, B_), 256, ATTN_SMEM_BYTES>>>(
      qh, ql, kh, kl, vh, vl, mask, semask, ah, al);

  // 5. output projection
  gemm_out_kernel<<<dim3(N_TOT / 128, M_TOT / 128), 256, GEMM_SMEM_BYTES>>>(
      ah, al, wh + 3 * NK, wl + 3 * NK, bm, out);
}